// round 11
// baseline (speedup 1.0000x reference)
#include <cuda_runtime.h>
#include <math.h>

#define NATOMS 1000
#define NPAIRS 10000
#define FDIM   64
#define NSH    9
#define NL     3
#define NRBF   20
#define CUTOFF 5.0f
#define CH     32

#define HDC __host__ __device__

// ---------------- device scratch: x after iteration 0 (no allocations) ----
__device__ float g_x1[NATOMS * NSH * FDIM];

// =================== compile-time real Clebsch-Gordan table ===============
HDC constexpr double cfact(int n) { double r = 1; for (int i = 2; i <= n; i++) r *= i; return r; }
HDC constexpr double csqrt_(double x) {
    if (x <= 0.0) return 0.0;
    double g = (x > 1.0) ? x : 1.0;
    for (int i = 0; i < 64; i++) g = 0.5 * (g + x / g);
    return g;
}
HDC constexpr int lof(int r) { return r >= 4 ? 2 : (r >= 1 ? 1 : 0); }

HDC constexpr double cg_c(int l1, int m1, int l2, int m2, int l3, int m3) {
    if (m3 != m1 + m2) return 0.0;
    int lmin = (l1 > l2) ? l1 - l2 : l2 - l1;
    if (l3 < lmin || l3 > l1 + l2) return 0.0;
    double pre = csqrt_((2.0 * l3 + 1.0) * cfact(l3 + l1 - l2) * cfact(l3 - l1 + l2) *
                        cfact(l1 + l2 - l3) / cfact(l1 + l2 + l3 + 1));
    pre *= csqrt_(cfact(l3 + m3) * cfact(l3 - m3) * cfact(l1 - m1) * cfact(l1 + m1) *
                  cfact(l2 - m2) * cfact(l2 + m2));
    double s = 0.0;
    for (int k = 0; k <= l1 + l2 - l3; k++) {
        int d2 = l1 - m1 - k, d3 = l2 + m2 - k, d4 = l3 - l2 + m1 + k, d5 = l3 - l1 - m2 + k;
        if (d2 < 0 || d3 < 0 || d4 < 0 || d5 < 0) continue;
        double denom = cfact(k) * cfact(l1 + l2 - l3 - k) * cfact(d2) * cfact(d3) *
                       cfact(d4) * cfact(d5);
        s += ((k & 1) ? -1.0 : 1.0) / denom;
    }
    return pre * s;
}

struct CRow { int n; int col[2]; double re[2]; double im[2]; };

HDC constexpr CRow urow(int r) {
    CRow s{}; int l = lof(r); int base = l * l + l; int mr = r - base;
    const double inv2 = 0.70710678118654752440;
    if (mr == 0) { s.n = 1; s.col[0] = base; s.re[0] = 1.0; s.im[0] = 0.0; }
    else if (mr > 0) {
        int m = mr; double sg = (m & 1) ? -1.0 : 1.0;
        s.n = 2;
        s.col[0] = base - m; s.re[0] = inv2;      s.im[0] = 0.0;
        s.col[1] = base + m; s.re[1] = sg * inv2; s.im[1] = 0.0;
    } else {
        int m = -mr; double sg = (m & 1) ? -1.0 : 1.0;
        s.n = 2;
        s.col[0] = base - m; s.re[0] = 0.0; s.im[0] = inv2;
        s.col[1] = base + m; s.re[1] = 0.0; s.im[1] = -sg * inv2;
    }
    return s;
}

HDC constexpr double real_cg(int o, int i2, int i3) {
    if (((lof(o) + lof(i2) + lof(i3)) & 1) != 0) return 0.0;
    CRow Ua = urow(i2), Ub = urow(i3), Uc = urow(o);
    int la = lof(i2), lb = lof(i3), lc = lof(o);
    int ba = la * la + la, bb = lb * lb + lb, bc = lc * lc + lc;
    double vre = 0.0;
    for (int i = 0; i < Ua.n; i++)
        for (int j = 0; j < Ub.n; j++)
            for (int k = 0; k < Uc.n; k++) {
                double cg = cg_c(la, Ua.col[i] - ba, lb, Ub.col[j] - bb, lc, Uc.col[k] - bc);
                if (cg == 0.0) continue;
                double t1r = Ua.re[i] * Ub.re[j] - Ua.im[i] * Ub.im[j];
                double t1i = Ua.re[i] * Ub.im[j] + Ua.im[i] * Ub.re[j];
                double tre = t1r * Uc.re[k] + t1i * Uc.im[k];
                vre += cg * tre;
            }
    return vre;
}

// ---- register-array contraction: acc[o] += cg * a[i2] * b[i3], fully unrolled ----
template <int LO, int HI>
struct Seg {
    static __device__ __forceinline__ void run(float (&acc)[9], const float (&a)[9],
                                               const float (&b)[9]) {
        if constexpr (HI - LO == 1) {
            constexpr int O = LO / 81, I2 = (LO / 9) % 9, I3 = LO % 9;
            constexpr double v = real_cg(O, I2, I3);
            if constexpr (v > 1e-9 || v < -1e-9) {
                acc[O] = fmaf((float)v, a[I2] * b[I3], acc[O]);
            }
        } else {
            Seg<LO, (LO + HI) / 2>::run(acc, a, b);
            Seg<(LO + HI) / 2, HI>::run(acc, a, b);
        }
    }
};

#define C0(o) ((float)real_cg(o, 0, o))

// ---------------- fused filter + message + update: 1 atom / 128-thread block ----
// Two 64-thread slots split the pair loop; update stage is executed redundantly.
// FIRST:  reads emb[Z] (iteration-0 x), writes x1
// !FIRST: reads x1, writes final x -> xw (d_out)
template <bool FIRST>
__global__ __launch_bounds__(128)
void fused_kernel(const int* __restrict__ idx_i, const int* __restrict__ idx_j,
                  const int* __restrict__ Z, const float* __restrict__ emb,
                  const float* __restrict__ r_ij,
                  const float* __restrict__ Wf, const float* __restrict__ bfv,
                  const float* __restrict__ xin, float* __restrict__ xw,
                  const float* __restrict__ W1, const float* __restrict__ W2,
                  const float* __restrict__ W3, const float* __restrict__ Wg,
                  const float* __restrict__ bg) {
    constexpr int T = FIRST ? 0 : 1;
    __shared__ float s_rad[CH][NRBF];   // rad * cut
    __shared__ float s_cut[CH];
    __shared__ float s_Y[CH][12];
    __shared__ int   s_j[CH];           // FIRST: Z[idx_j[p]]; else idx_j[p]
    __shared__ float sb0[NSH * FDIM];
    __shared__ float sb1[NSH * FDIM];

    int tid = threadIdx.x;
    int f = tid & 63;
    int slot = tid >> 6;                // 0 or 1
    int a = blockIdx.x;

    // segment of sorted idx_i equal to a
    int lo = 0, hi = NPAIRS;
    while (lo < hi) { int m = (lo + hi) >> 1; if (idx_i[m] < a) lo = m + 1; else hi = m; }
    int pstart = lo;
    hi = NPAIRS;
    while (lo < hi) { int m = (lo + hi) >> 1; if (idx_i[m] <= a) lo = m + 1; else hi = m; }
    int pend = lo;

    // preload Wf column f (this t) + bias
    float wfr[NL][NRBF];
    {
        const float* wf = Wf + T * (NRBF * NL * FDIM) + f;
        #pragma unroll
        for (int k = 0; k < NRBF; k++)
            #pragma unroll
            for (int l = 0; l < NL; l++)
                wfr[l][k] = __ldg(wf + k * NL * FDIM + l * FDIM);
    }
    float bfl[NL];
    #pragma unroll
    for (int l = 0; l < NL; l++) bfl[l] = __ldg(bfv + T * NL * FDIM + l * FDIM + f);

    float dxr[9];
    #pragma unroll
    for (int o = 0; o < 9; o++) dxr[o] = 0.f;

    const float width = CUTOFF / (NRBF - 1);
    const float alpha = -0.5f / (width * width);

    for (int c = pstart; c < pend; c += CH) {
        int n = min(CH, pend - c);
        if (tid < n) {
            int p = c + tid;
            int jj = __ldg(idx_j + p);
            s_j[tid] = FIRST ? __ldg(Z + jj) : jj;
            float rx = __ldg(r_ij + 3 * p), ry = __ldg(r_ij + 3 * p + 1),
                  rz = __ldg(r_ij + 3 * p + 2);
            float d = sqrtf(rx * rx + ry * ry + rz * rz);
            float cut = (d < CUTOFF)
                      ? 0.5f * (cosf(d * (3.14159265358979323846f / CUTOFF)) + 1.f) : 0.f;
            s_cut[tid] = cut;
            #pragma unroll
            for (int k = 0; k < NRBF; k++) {
                float dd = d - width * (float)k;
                s_rad[tid][k] = __expf(alpha * dd * dd) * cut;
            }
            float inv = 1.f / d;
            float x = rx * inv, y = ry * inv, z = rz * inv;
            const float c0 = 0.28209479177387814f;
            const float c1 = 0.4886025119029199f;
            const float c2 = 1.0925484305920792f;
            const float c3 = 0.31539156525252005f;
            const float c4 = 0.5462742152960396f;
            s_Y[tid][0] = c0;
            s_Y[tid][1] = c1 * y;
            s_Y[tid][2] = c1 * z;
            s_Y[tid][3] = c1 * x;
            s_Y[tid][4] = c2 * x * y;
            s_Y[tid][5] = c2 * y * z;
            s_Y[tid][6] = c3 * (3.f * z * z - 1.f);
            s_Y[tid][7] = c2 * x * z;
            s_Y[tid][8] = c4 * (x * x - y * y);
        }
        __syncthreads();

        for (int i = slot; i < n; i += 2) {
            float cut = s_cut[i];
            float w0 = bfl[0] * cut, w1v = bfl[1] * cut, w2v = bfl[2] * cut;
            #pragma unroll
            for (int k = 0; k < NRBF; k++) {
                float r = s_rad[i][k];
                w0  = fmaf(r, wfr[0][k], w0);
                w1v = fmaf(r, wfr[1][k], w1v);
                w2v = fmaf(r, wfr[2][k], w2v);
            }
            float tv[9];
            tv[0] = s_Y[i][0] * w0;
            tv[1] = s_Y[i][1] * w1v;
            tv[2] = s_Y[i][2] * w1v;
            tv[3] = s_Y[i][3] * w1v;
            tv[4] = s_Y[i][4] * w2v;
            tv[5] = s_Y[i][5] * w2v;
            tv[6] = s_Y[i][6] * w2v;
            tv[7] = s_Y[i][7] * w2v;
            tv[8] = s_Y[i][8] * w2v;

            if constexpr (FIRST) {
                float x0 = __ldg(emb + s_j[i] * FDIM + f);
                const float cc[9] = {C0(0), C0(1), C0(2), C0(3), C0(4),
                                     C0(5), C0(6), C0(7), C0(8)};
                #pragma unroll
                for (int o = 0; o < 9; o++)
                    dxr[o] = fmaf(cc[o] * x0, tv[o], dxr[o]);
            } else {
                const float* xj = xin + s_j[i] * (NSH * FDIM) + f;
                float xr[9];
                #pragma unroll
                for (int o = 0; o < 9; o++) xr[o] = __ldg(xj + o * 64);
                Seg<0, 729>::run(dxr, xr, tv);
            }
        }
        __syncthreads();
    }

    // ---- reduce the two slot partials ----
    {
        float* sbP = slot ? sb1 : sb0;
        #pragma unroll
        for (int o = 0; o < 9; o++) sbP[o * 64 + f] = dxr[o];
    }
    __syncthreads();
    #pragma unroll
    for (int o = 0; o < 9; o++) dxr[o] = sb0[o * 64 + f] + sb1[o * 64 + f];

    // ---- update stage (both slots redundantly) ----
    const float* w1 = W1 + T * 4096 + f;
    const float* w2 = W2 + T * 4096 + f;
    const float* w3 = W3 + T * 4096 + f;
    const float* wg = Wg + T * 12288 + f;
    const float* bgp = bg + T * 192 + f;
    int base = a * (NSH * FDIM);

    __syncthreads();   // sb0/sb1 partial reads complete before overwrite
    if (slot == 0) {
        #pragma unroll
        for (int o = 0; o < 9; o++) sb0[o * 64 + f] = dxr[o];
    }

    float w[64];
    #pragma unroll
    for (int k = 0; k < 64; k++) w[k] = __ldg(w1 + k * 64);
    __syncthreads();

    float ddx[9];
    const float4* a0p = reinterpret_cast<const float4*>(sb0);
    #pragma unroll
    for (int o = 0; o < 9; o++) {
        float s = 0.f;
        #pragma unroll
        for (int k4 = 0; k4 < 16; k4++) {
            float4 v = a0p[o * 16 + k4];
            s = fmaf(v.x, w[k4 * 4 + 0], s);
            s = fmaf(v.y, w[k4 * 4 + 1], s);
            s = fmaf(v.z, w[k4 * 4 + 2], s);
            s = fmaf(v.w, w[k4 * 4 + 3], s);
        }
        ddx[o] = s;
    }

    float tp[9];
    #pragma unroll
    for (int o = 0; o < 9; o++) tp[o] = dxr[o];
    Seg<0, 729>::run(tp, dxr, ddx);

    __syncthreads();   // GEMV1 reads of sb1 complete before overwrite? (sb1 holds slot1 partial; safe) 
    if (slot == 0) {
        #pragma unroll
        for (int o = 0; o < 9; o++) sb1[o * 64 + f] = tp[o];
    }

    #pragma unroll
    for (int k = 0; k < 64; k++) w[k] = __ldg(w2 + k * 64);
    __syncthreads();

    float dx2[9];
    const float4* a1p = reinterpret_cast<const float4*>(sb1);
    #pragma unroll
    for (int o = 0; o < 9; o++) {
        float s = 0.f;
        #pragma unroll
        for (int k4 = 0; k4 < 16; k4++) {
            float4 v = a1p[o * 16 + k4];
            s = fmaf(v.x, w[k4 * 4 + 0], s);
            s = fmaf(v.y, w[k4 * 4 + 1], s);
            s = fmaf(v.z, w[k4 * 4 + 2], s);
            s = fmaf(v.w, w[k4 * 4 + 3], s);
        }
        dx2[o] = s;
    }
    __syncthreads();
    if (tid < 64) sb0[f] = dx2[0];
    __syncthreads();

    float g0 = bgp[0], g1 = bgp[64], g2 = bgp[128];
    {
        const float4* r0 = reinterpret_cast<const float4*>(sb0);
        #pragma unroll
        for (int k4 = 0; k4 < 16; k4++) {
            float4 v = r0[k4];
            const float* wgk = wg + (k4 * 4) * 192;
            g0 = fmaf(v.x, __ldg(wgk), g0);
            g1 = fmaf(v.x, __ldg(wgk + 64), g1);
            g2 = fmaf(v.x, __ldg(wgk + 128), g2);
            g0 = fmaf(v.y, __ldg(wgk + 192), g0);
            g1 = fmaf(v.y, __ldg(wgk + 256), g1);
            g2 = fmaf(v.y, __ldg(wgk + 320), g2);
            g0 = fmaf(v.z, __ldg(wgk + 384), g0);
            g1 = fmaf(v.z, __ldg(wgk + 448), g1);
            g2 = fmaf(v.z, __ldg(wgk + 512), g2);
            g0 = fmaf(v.w, __ldg(wgk + 576), g0);
            g1 = fmaf(v.w, __ldg(wgk + 640), g1);
            g2 = fmaf(v.w, __ldg(wgk + 704), g2);
        }
    }
    float sg[3];
    sg[0] = 1.f / (1.f + __expf(-g0));
    sg[1] = 1.f / (1.f + __expf(-g1));
    sg[2] = 1.f / (1.f + __expf(-g2));

    __syncthreads();   // gate reads of sb1 (GEMV2 inputs) done before gated overwrite
    if (slot == 0) {
        #pragma unroll
        for (int o = 0; o < 9; o++) {
            int l = (o >= 4) ? 2 : ((o >= 1) ? 1 : 0);
            sb1[o * 64 + f] = dx2[o] * sg[l];
        }
    }

    #pragma unroll
    for (int k = 0; k < 64; k++) w[k] = __ldg(w3 + k * 64);
    __syncthreads();

    #pragma unroll
    for (int o = 0; o < 9; o++) {
        float s = 0.f;
        #pragma unroll
        for (int k4 = 0; k4 < 16; k4++) {
            float4 v = a1p[o * 16 + k4];
            s = fmaf(v.x, w[k4 * 4 + 0], s);
            s = fmaf(v.y, w[k4 * 4 + 1], s);
            s = fmaf(v.z, w[k4 * 4 + 2], s);
            s = fmaf(v.w, w[k4 * 4 + 3], s);
        }
        if ((o & 1) == slot) {
            float prev;
            if constexpr (FIRST) {
                prev = (o == 0) ? __ldg(emb + __ldg(Z + a) * FDIM + f) : 0.f;
            } else {
                prev = __ldg(xin + base + o * 64 + f);
            }
            xw[base + o * 64 + f] = prev + s;
        }
    }
}

// ---------------- launch ---------------------------------------------------
extern "C" void kernel_launch(void* const* d_in, const int* in_sizes, int n_in,
                              void* d_out, int out_size) {
    const int*   Z    = (const int*)d_in[0];
    const float* r_ij = (const float*)d_in[1];
    const int*   idxi = (const int*)d_in[2];
    const int*   idxj = (const int*)d_in[3];
    const float* emb  = (const float*)d_in[4];
    const float* Wf   = (const float*)d_in[5];
    const float* bf   = (const float*)d_in[6];
    const float* W1   = (const float*)d_in[7];
    const float* W2   = (const float*)d_in[8];
    const float* W3   = (const float*)d_in[9];
    const float* Wg   = (const float*)d_in[10];
    const float* bg   = (const float*)d_in[11];
    float* xout = (float*)d_out;

    float* x1;
    cudaGetSymbolAddress((void**)&x1, g_x1);

    // iter 0: emb -> g_x1 ; iter 1: g_x1 -> xout (no cross-launch aliasing)
    fused_kernel<true ><<<NATOMS, 128>>>(idxi, idxj, Z, emb, r_ij, Wf, bf,
                                         nullptr, x1, W1, W2, W3, Wg, bg);
    fused_kernel<false><<<NATOMS, 128>>>(idxi, idxj, Z, emb, r_ij, Wf, bf,
                                         x1, xout, W1, W2, W3, Wg, bg);
}

// round 12
// speedup vs baseline: 1.3072x; 1.3072x over previous
#include <cuda_runtime.h>
#include <math.h>

#define NATOMS 1000
#define NPAIRS 10000
#define FDIM   64
#define NSH    9
#define NL     3
#define NRBF   20
#define CUTOFF 5.0f
#define CH     32

#define HDC __host__ __device__

// ---------------- device scratch: x after iteration 0 (no allocations) ----
__device__ float g_x1[NATOMS * NSH * FDIM];

// =================== compile-time real Clebsch-Gordan table ===============
HDC constexpr double cfact(int n) { double r = 1; for (int i = 2; i <= n; i++) r *= i; return r; }
HDC constexpr double csqrt_(double x) {
    if (x <= 0.0) return 0.0;
    double g = (x > 1.0) ? x : 1.0;
    for (int i = 0; i < 64; i++) g = 0.5 * (g + x / g);
    return g;
}
HDC constexpr int lof(int r) { return r >= 4 ? 2 : (r >= 1 ? 1 : 0); }

HDC constexpr double cg_c(int l1, int m1, int l2, int m2, int l3, int m3) {
    if (m3 != m1 + m2) return 0.0;
    int lmin = (l1 > l2) ? l1 - l2 : l2 - l1;
    if (l3 < lmin || l3 > l1 + l2) return 0.0;
    double pre = csqrt_((2.0 * l3 + 1.0) * cfact(l3 + l1 - l2) * cfact(l3 - l1 + l2) *
                        cfact(l1 + l2 - l3) / cfact(l1 + l2 + l3 + 1));
    pre *= csqrt_(cfact(l3 + m3) * cfact(l3 - m3) * cfact(l1 - m1) * cfact(l1 + m1) *
                  cfact(l2 - m2) * cfact(l2 + m2));
    double s = 0.0;
    for (int k = 0; k <= l1 + l2 - l3; k++) {
        int d2 = l1 - m1 - k, d3 = l2 + m2 - k, d4 = l3 - l2 + m1 + k, d5 = l3 - l1 - m2 + k;
        if (d2 < 0 || d3 < 0 || d4 < 0 || d5 < 0) continue;
        double denom = cfact(k) * cfact(l1 + l2 - l3 - k) * cfact(d2) * cfact(d3) *
                       cfact(d4) * cfact(d5);
        s += ((k & 1) ? -1.0 : 1.0) / denom;
    }
    return pre * s;
}

struct CRow { int n; int col[2]; double re[2]; double im[2]; };

HDC constexpr CRow urow(int r) {
    CRow s{}; int l = lof(r); int base = l * l + l; int mr = r - base;
    const double inv2 = 0.70710678118654752440;
    if (mr == 0) { s.n = 1; s.col[0] = base; s.re[0] = 1.0; s.im[0] = 0.0; }
    else if (mr > 0) {
        int m = mr; double sg = (m & 1) ? -1.0 : 1.0;
        s.n = 2;
        s.col[0] = base - m; s.re[0] = inv2;      s.im[0] = 0.0;
        s.col[1] = base + m; s.re[1] = sg * inv2; s.im[1] = 0.0;
    } else {
        int m = -mr; double sg = (m & 1) ? -1.0 : 1.0;
        s.n = 2;
        s.col[0] = base - m; s.re[0] = 0.0; s.im[0] = inv2;
        s.col[1] = base + m; s.re[1] = 0.0; s.im[1] = -sg * inv2;
    }
    return s;
}

HDC constexpr double real_cg(int o, int i2, int i3) {
    if (((lof(o) + lof(i2) + lof(i3)) & 1) != 0) return 0.0;
    CRow Ua = urow(i2), Ub = urow(i3), Uc = urow(o);
    int la = lof(i2), lb = lof(i3), lc = lof(o);
    int ba = la * la + la, bb = lb * lb + lb, bc = lc * lc + lc;
    double vre = 0.0;
    for (int i = 0; i < Ua.n; i++)
        for (int j = 0; j < Ub.n; j++)
            for (int k = 0; k < Uc.n; k++) {
                double cg = cg_c(la, Ua.col[i] - ba, lb, Ub.col[j] - bb, lc, Uc.col[k] - bc);
                if (cg == 0.0) continue;
                double t1r = Ua.re[i] * Ub.re[j] - Ua.im[i] * Ub.im[j];
                double t1i = Ua.re[i] * Ub.im[j] + Ua.im[i] * Ub.re[j];
                double tre = t1r * Uc.re[k] + t1i * Uc.im[k];
                vre += cg * tre;
            }
    return vre;
}

// ---- register-array contraction: acc[o] += cg * a[i2] * b[i3], fully unrolled ----
template <int LO, int HI>
struct Seg {
    static __device__ __forceinline__ void run(float (&acc)[9], const float (&a)[9],
                                               const float (&b)[9]) {
        if constexpr (HI - LO == 1) {
            constexpr int O = LO / 81, I2 = (LO / 9) % 9, I3 = LO % 9;
            constexpr double v = real_cg(O, I2, I3);
            if constexpr (v > 1e-9 || v < -1e-9) {
                acc[O] = fmaf((float)v, a[I2] * b[I3], acc[O]);
            }
        } else {
            Seg<LO, (LO + HI) / 2>::run(acc, a, b);
            Seg<(LO + HI) / 2, HI>::run(acc, a, b);
        }
    }
};

#define C0(o) ((float)real_cg(o, 0, o))

// ---------------- fused filter + message + update: 1 atom / 64-thread block ----
// FIRST:  reads emb[Z] (iteration-0 x), writes x1
// !FIRST: reads x1, writes final x -> xw (d_out)
template <bool FIRST>
__global__ __launch_bounds__(64)
void fused_kernel(const int* __restrict__ idx_i, const int* __restrict__ idx_j,
                  const int* __restrict__ Z, const float* __restrict__ emb,
                  const float* __restrict__ r_ij,
                  const float* __restrict__ Wf, const float* __restrict__ bfv,
                  const float* __restrict__ xin, float* __restrict__ xw,
                  const float* __restrict__ W1, const float* __restrict__ W2,
                  const float* __restrict__ W3, const float* __restrict__ Wg,
                  const float* __restrict__ bg) {
    constexpr int T = FIRST ? 0 : 1;
    __shared__ float s_rad[CH][NRBF];   // rad * cut
    __shared__ float s_cut[CH];
    __shared__ float s_Y[CH][12];
    __shared__ int   s_j[CH];           // FIRST: Z[idx_j[p]]; else idx_j[p]
    __shared__ float sb0[NSH * FDIM];
    __shared__ float sb1[NSH * FDIM];

    int f = threadIdx.x;
    int a = blockIdx.x;

    // segment of sorted idx_i equal to a
    int lo = 0, hi = NPAIRS;
    while (lo < hi) { int m = (lo + hi) >> 1; if (idx_i[m] < a) lo = m + 1; else hi = m; }
    int pstart = lo;
    hi = NPAIRS;
    while (lo < hi) { int m = (lo + hi) >> 1; if (idx_i[m] <= a) lo = m + 1; else hi = m; }
    int pend = lo;

    int base = a * (NSH * FDIM);

    // prefetch residual early — consumed only at the very end
    float prev[9];
    if constexpr (FIRST) {
        float e0 = __ldg(emb + __ldg(Z + a) * FDIM + f);
        prev[0] = e0;
        #pragma unroll
        for (int o = 1; o < 9; o++) prev[o] = 0.f;
    } else {
        #pragma unroll
        for (int o = 0; o < 9; o++) prev[o] = __ldg(xin + base + o * 64 + f);
    }

    // preload Wf column f (this t) + bias
    float wfr[NL][NRBF];
    {
        const float* wf = Wf + T * (NRBF * NL * FDIM) + f;
        #pragma unroll
        for (int k = 0; k < NRBF; k++)
            #pragma unroll
            for (int l = 0; l < NL; l++)
                wfr[l][k] = __ldg(wf + k * NL * FDIM + l * FDIM);
    }
    float bfl[NL];
    #pragma unroll
    for (int l = 0; l < NL; l++) bfl[l] = __ldg(bfv + T * NL * FDIM + l * FDIM + f);

    float dxr[9];
    #pragma unroll
    for (int o = 0; o < 9; o++) dxr[o] = 0.f;

    const float width = CUTOFF / (NRBF - 1);
    const float alpha = -0.5f / (width * width);

    for (int c = pstart; c < pend; c += CH) {
        int n = min(CH, pend - c);
        if (f < n) {
            int p = c + f;
            int jj = __ldg(idx_j + p);
            s_j[f] = FIRST ? __ldg(Z + jj) : jj;
            float rx = __ldg(r_ij + 3 * p), ry = __ldg(r_ij + 3 * p + 1),
                  rz = __ldg(r_ij + 3 * p + 2);
            float d = sqrtf(rx * rx + ry * ry + rz * rz);
            float cut = (d < CUTOFF)
                      ? 0.5f * (cosf(d * (3.14159265358979323846f / CUTOFF)) + 1.f) : 0.f;
            s_cut[f] = cut;
            #pragma unroll
            for (int k = 0; k < NRBF; k++) {
                float dd = d - width * (float)k;
                s_rad[f][k] = __expf(alpha * dd * dd) * cut;
            }
            float inv = 1.f / d;
            float x = rx * inv, y = ry * inv, z = rz * inv;
            const float c0 = 0.28209479177387814f;
            const float c1 = 0.4886025119029199f;
            const float c2 = 1.0925484305920792f;
            const float c3 = 0.31539156525252005f;
            const float c4 = 0.5462742152960396f;
            s_Y[f][0] = c0;
            s_Y[f][1] = c1 * y;
            s_Y[f][2] = c1 * z;
            s_Y[f][3] = c1 * x;
            s_Y[f][4] = c2 * x * y;
            s_Y[f][5] = c2 * y * z;
            s_Y[f][6] = c3 * (3.f * z * z - 1.f);
            s_Y[f][7] = c2 * x * z;
            s_Y[f][8] = c4 * (x * x - y * y);
        }
        __syncthreads();

        // software-pipelined over pairs: prefetch xj(i+1) during compute(i)
        float xr[9];
        if constexpr (FIRST) {
            xr[0] = __ldg(emb + s_j[0] * FDIM + f);
        } else {
            const float* xj = xin + s_j[0] * (NSH * FDIM) + f;
            #pragma unroll
            for (int o = 0; o < 9; o++) xr[o] = __ldg(xj + o * 64);
        }

        for (int i = 0; i < n; i++) {
            // prefetch next pair's features first (independent of this iteration)
            float xrn[9];
            if (i + 1 < n) {
                if constexpr (FIRST) {
                    xrn[0] = __ldg(emb + s_j[i + 1] * FDIM + f);
                } else {
                    const float* xjn = xin + s_j[i + 1] * (NSH * FDIM) + f;
                    #pragma unroll
                    for (int o = 0; o < 9; o++) xrn[o] = __ldg(xjn + o * 64);
                }
            }

            float cut = s_cut[i];
            float w0 = bfl[0] * cut, w1v = bfl[1] * cut, w2v = bfl[2] * cut;
            #pragma unroll
            for (int k = 0; k < NRBF; k++) {
                float r = s_rad[i][k];
                w0  = fmaf(r, wfr[0][k], w0);
                w1v = fmaf(r, wfr[1][k], w1v);
                w2v = fmaf(r, wfr[2][k], w2v);
            }
            float tv[9];
            tv[0] = s_Y[i][0] * w0;
            tv[1] = s_Y[i][1] * w1v;
            tv[2] = s_Y[i][2] * w1v;
            tv[3] = s_Y[i][3] * w1v;
            tv[4] = s_Y[i][4] * w2v;
            tv[5] = s_Y[i][5] * w2v;
            tv[6] = s_Y[i][6] * w2v;
            tv[7] = s_Y[i][7] * w2v;
            tv[8] = s_Y[i][8] * w2v;

            if constexpr (FIRST) {
                const float cc[9] = {C0(0), C0(1), C0(2), C0(3), C0(4),
                                     C0(5), C0(6), C0(7), C0(8)};
                #pragma unroll
                for (int o = 0; o < 9; o++)
                    dxr[o] = fmaf(cc[o] * xr[0], tv[o], dxr[o]);
            } else {
                Seg<0, 729>::run(dxr, xr, tv);
            }

            if constexpr (FIRST) {
                xr[0] = xrn[0];
            } else {
                #pragma unroll
                for (int o = 0; o < 9; o++) xr[o] = xrn[o];
            }
        }
        __syncthreads();
    }

    // ---- update stage ----
    const float* w1 = W1 + T * 4096 + f;
    const float* w2 = W2 + T * 4096 + f;
    const float* w3 = W3 + T * 4096 + f;
    const float* wg = Wg + T * 12288 + f;
    const float* bgp = bg + T * 192 + f;

    #pragma unroll
    for (int o = 0; o < 9; o++) sb0[o * 64 + f] = dxr[o];

    float w[64];
    #pragma unroll
    for (int k = 0; k < 64; k++) w[k] = __ldg(w1 + k * 64);
    __syncthreads();

    float ddx[9];
    const float4* a0p = reinterpret_cast<const float4*>(sb0);
    #pragma unroll
    for (int o = 0; o < 9; o++) {
        float s = 0.f;
        #pragma unroll
        for (int k4 = 0; k4 < 16; k4++) {
            float4 v = a0p[o * 16 + k4];
            s = fmaf(v.x, w[k4 * 4 + 0], s);
            s = fmaf(v.y, w[k4 * 4 + 1], s);
            s = fmaf(v.z, w[k4 * 4 + 2], s);
            s = fmaf(v.w, w[k4 * 4 + 3], s);
        }
        ddx[o] = s;
    }

    float tp[9];
    #pragma unroll
    for (int o = 0; o < 9; o++) tp[o] = dxr[o];
    Seg<0, 729>::run(tp, dxr, ddx);

    #pragma unroll
    for (int o = 0; o < 9; o++) sb1[o * 64 + f] = tp[o];

    #pragma unroll
    for (int k = 0; k < 64; k++) w[k] = __ldg(w2 + k * 64);
    __syncthreads();

    float dx2[9];
    const float4* a1p = reinterpret_cast<const float4*>(sb1);
    #pragma unroll
    for (int o = 0; o < 9; o++) {
        float s = 0.f;
        #pragma unroll
        for (int k4 = 0; k4 < 16; k4++) {
            float4 v = a1p[o * 16 + k4];
            s = fmaf(v.x, w[k4 * 4 + 0], s);
            s = fmaf(v.y, w[k4 * 4 + 1], s);
            s = fmaf(v.z, w[k4 * 4 + 2], s);
            s = fmaf(v.w, w[k4 * 4 + 3], s);
        }
        dx2[o] = s;
    }
    sb0[f] = dx2[0];
    __syncthreads();

    float g0 = bgp[0], g1 = bgp[64], g2 = bgp[128];
    {
        const float4* r0 = reinterpret_cast<const float4*>(sb0);
        #pragma unroll
        for (int k4 = 0; k4 < 16; k4++) {
            float4 v = r0[k4];
            const float* wgk = wg + (k4 * 4) * 192;
            g0 = fmaf(v.x, __ldg(wgk), g0);
            g1 = fmaf(v.x, __ldg(wgk + 64), g1);
            g2 = fmaf(v.x, __ldg(wgk + 128), g2);
            g0 = fmaf(v.y, __ldg(wgk + 192), g0);
            g1 = fmaf(v.y, __ldg(wgk + 256), g1);
            g2 = fmaf(v.y, __ldg(wgk + 320), g2);
            g0 = fmaf(v.z, __ldg(wgk + 384), g0);
            g1 = fmaf(v.z, __ldg(wgk + 448), g1);
            g2 = fmaf(v.z, __ldg(wgk + 512), g2);
            g0 = fmaf(v.w, __ldg(wgk + 576), g0);
            g1 = fmaf(v.w, __ldg(wgk + 640), g1);
            g2 = fmaf(v.w, __ldg(wgk + 704), g2);
        }
    }
    float sg[3];
    sg[0] = 1.f / (1.f + __expf(-g0));
    sg[1] = 1.f / (1.f + __expf(-g1));
    sg[2] = 1.f / (1.f + __expf(-g2));

    #pragma unroll
    for (int o = 0; o < 9; o++) {
        int l = (o >= 4) ? 2 : ((o >= 1) ? 1 : 0);
        sb1[o * 64 + f] = dx2[o] * sg[l];
    }

    #pragma unroll
    for (int k = 0; k < 64; k++) w[k] = __ldg(w3 + k * 64);
    __syncthreads();

    #pragma unroll
    for (int o = 0; o < 9; o++) {
        float s = 0.f;
        #pragma unroll
        for (int k4 = 0; k4 < 16; k4++) {
            float4 v = a1p[o * 16 + k4];
            s = fmaf(v.x, w[k4 * 4 + 0], s);
            s = fmaf(v.y, w[k4 * 4 + 1], s);
            s = fmaf(v.z, w[k4 * 4 + 2], s);
            s = fmaf(v.w, w[k4 * 4 + 3], s);
        }
        xw[base + o * 64 + f] = prev[o] + s;
    }
}

// ---------------- launch ---------------------------------------------------
extern "C" void kernel_launch(void* const* d_in, const int* in_sizes, int n_in,
                              void* d_out, int out_size) {
    const int*   Z    = (const int*)d_in[0];
    const float* r_ij = (const float*)d_in[1];
    const int*   idxi = (const int*)d_in[2];
    const int*   idxj = (const int*)d_in[3];
    const float* emb  = (const float*)d_in[4];
    const float* Wf   = (const float*)d_in[5];
    const float* bf   = (const float*)d_in[6];
    const float* W1   = (const float*)d_in[7];
    const float* W2   = (const float*)d_in[8];
    const float* W3   = (const float*)d_in[9];
    const float* Wg   = (const float*)d_in[10];
    const float* bg   = (const float*)d_in[11];
    float* xout = (float*)d_out;

    float* x1;
    cudaGetSymbolAddress((void**)&x1, g_x1);

    // iter 0: emb -> g_x1 ; iter 1: g_x1 -> xout (no cross-launch aliasing)
    fused_kernel<true ><<<NATOMS, 64>>>(idxi, idxj, Z, emb, r_ij, Wf, bf,
                                        nullptr, x1, W1, W2, W3, Wg, bg);
    fused_kernel<false><<<NATOMS, 64>>>(idxi, idxj, Z, emb, r_ij, Wf, bf,
                                        x1, xout, W1, W2, W3, Wg, bg);
}

// round 13
// speedup vs baseline: 1.4755x; 1.1288x over previous
#include <cuda_runtime.h>
#include <math.h>

#define NATOMS 1000
#define NPAIRS 10000
#define FDIM   64
#define NSH    9
#define NL     3
#define NRBF   20
#define CUTOFF 5.0f
#define CH     32

#define HDC __host__ __device__

// ---------------- device scratch (no allocations) -------------------------
__device__ float g_x1[NATOMS * NSH * FDIM];
__device__ int2  g_seg[NATOMS];

// =================== compile-time real Clebsch-Gordan table ===============
HDC constexpr double cfact(int n) { double r = 1; for (int i = 2; i <= n; i++) r *= i; return r; }
HDC constexpr double csqrt_(double x) {
    if (x <= 0.0) return 0.0;
    double g = (x > 1.0) ? x : 1.0;
    for (int i = 0; i < 64; i++) g = 0.5 * (g + x / g);
    return g;
}
HDC constexpr int lof(int r) { return r >= 4 ? 2 : (r >= 1 ? 1 : 0); }

HDC constexpr double cg_c(int l1, int m1, int l2, int m2, int l3, int m3) {
    if (m3 != m1 + m2) return 0.0;
    int lmin = (l1 > l2) ? l1 - l2 : l2 - l1;
    if (l3 < lmin || l3 > l1 + l2) return 0.0;
    double pre = csqrt_((2.0 * l3 + 1.0) * cfact(l3 + l1 - l2) * cfact(l3 - l1 + l2) *
                        cfact(l1 + l2 - l3) / cfact(l1 + l2 + l3 + 1));
    pre *= csqrt_(cfact(l3 + m3) * cfact(l3 - m3) * cfact(l1 - m1) * cfact(l1 + m1) *
                  cfact(l2 - m2) * cfact(l2 + m2));
    double s = 0.0;
    for (int k = 0; k <= l1 + l2 - l3; k++) {
        int d2 = l1 - m1 - k, d3 = l2 + m2 - k, d4 = l3 - l2 + m1 + k, d5 = l3 - l1 - m2 + k;
        if (d2 < 0 || d3 < 0 || d4 < 0 || d5 < 0) continue;
        double denom = cfact(k) * cfact(l1 + l2 - l3 - k) * cfact(d2) * cfact(d3) *
                       cfact(d4) * cfact(d5);
        s += ((k & 1) ? -1.0 : 1.0) / denom;
    }
    return pre * s;
}

struct CRow { int n; int col[2]; double re[2]; double im[2]; };

HDC constexpr CRow urow(int r) {
    CRow s{}; int l = lof(r); int base = l * l + l; int mr = r - base;
    const double inv2 = 0.70710678118654752440;
    if (mr == 0) { s.n = 1; s.col[0] = base; s.re[0] = 1.0; s.im[0] = 0.0; }
    else if (mr > 0) {
        int m = mr; double sg = (m & 1) ? -1.0 : 1.0;
        s.n = 2;
        s.col[0] = base - m; s.re[0] = inv2;      s.im[0] = 0.0;
        s.col[1] = base + m; s.re[1] = sg * inv2; s.im[1] = 0.0;
    } else {
        int m = -mr; double sg = (m & 1) ? -1.0 : 1.0;
        s.n = 2;
        s.col[0] = base - m; s.re[0] = 0.0; s.im[0] = inv2;
        s.col[1] = base + m; s.re[1] = 0.0; s.im[1] = -sg * inv2;
    }
    return s;
}

HDC constexpr double real_cg(int o, int i2, int i3) {
    if (((lof(o) + lof(i2) + lof(i3)) & 1) != 0) return 0.0;
    CRow Ua = urow(i2), Ub = urow(i3), Uc = urow(o);
    int la = lof(i2), lb = lof(i3), lc = lof(o);
    int ba = la * la + la, bb = lb * lb + lb, bc = lc * lc + lc;
    double vre = 0.0;
    for (int i = 0; i < Ua.n; i++)
        for (int j = 0; j < Ub.n; j++)
            for (int k = 0; k < Uc.n; k++) {
                double cg = cg_c(la, Ua.col[i] - ba, lb, Ub.col[j] - bb, lc, Uc.col[k] - bc);
                if (cg == 0.0) continue;
                double t1r = Ua.re[i] * Ub.re[j] - Ua.im[i] * Ub.im[j];
                double t1i = Ua.re[i] * Ub.im[j] + Ua.im[i] * Ub.re[j];
                double tre = t1r * Uc.re[k] + t1i * Uc.im[k];
                vre += cg * tre;
            }
    return vre;
}

// ---- register-array contraction: acc[o] += cg * a[i2] * b[i3], fully unrolled ----
template <int LO, int HI>
struct Seg {
    static __device__ __forceinline__ void run(float (&acc)[9], const float (&a)[9],
                                               const float (&b)[9]) {
        if constexpr (HI - LO == 1) {
            constexpr int O = LO / 81, I2 = (LO / 9) % 9, I3 = LO % 9;
            constexpr double v = real_cg(O, I2, I3);
            if constexpr (v > 1e-9 || v < -1e-9) {
                acc[O] = fmaf((float)v, a[I2] * b[I3], acc[O]);
            }
        } else {
            Seg<LO, (LO + HI) / 2>::run(acc, a, b);
            Seg<(LO + HI) / 2, HI>::run(acc, a, b);
        }
    }
};

#define C0(o) ((float)real_cg(o, 0, o))

// ---- warp-parallel bound search over sorted idx_i (executed by one full warp) ----
// upper=false: first pos with idx[pos] >= a ; upper=true: first pos with idx[pos] > a
__device__ __forceinline__ int warp_bound(const int* __restrict__ idx, int a, bool upper) {
    int lane = threadIdx.x & 31;
    int lo = 0, hiB = NPAIRS;            // boundary B in [lo, hiB]
    while (hiB > lo) {
        int step = (hiB - lo + 31) >> 5;
        int pos = lo + lane * step;
        bool lt = false;
        if (pos < hiB) {
            int v = __ldg(idx + pos);
            lt = upper ? (v <= a) : (v < a);
        }
        unsigned m = __ballot_sync(0xffffffffu, lt);
        int c = __popc(m);
        if (c == 0) {
            hiB = lo;                    // B = lo
        } else {
            int nlo = lo + (c - 1) * step + 1;
            int nhi = (c < 32) ? min(lo + c * step, hiB) : hiB;
            lo = nlo; hiB = nhi;
        }
    }
    return lo;
}

// ---------------- fused filter + message + update: 1 atom / 64-thread block ----
// FIRST:  reads emb[Z] (iteration-0 x), computes segment (warp search), stores g_seg,
//         writes x1
// !FIRST: reads g_seg + x1, writes final x -> xw (d_out)
template <bool FIRST>
__global__ __launch_bounds__(64)
void fused_kernel(const int* __restrict__ idx_i, const int* __restrict__ idx_j,
                  const int* __restrict__ Z, const float* __restrict__ emb,
                  const float* __restrict__ r_ij,
                  const float* __restrict__ Wf, const float* __restrict__ bfv,
                  const float* __restrict__ xin, float* __restrict__ xw,
                  const float* __restrict__ W1, const float* __restrict__ W2,
                  const float* __restrict__ W3, const float* __restrict__ Wg,
                  const float* __restrict__ bg) {
    constexpr int T = FIRST ? 0 : 1;
    __shared__ float s_rad[CH][NRBF];   // rad * cut
    __shared__ float s_cut[CH];
    __shared__ float s_Y[CH][12];
    __shared__ int   s_j[CH];           // FIRST: Z[idx_j[p]]; else idx_j[p]
    __shared__ int   s_seg[2];
    __shared__ float sb0[NSH * FDIM];
    __shared__ float sb1[NSH * FDIM];

    int f = threadIdx.x;
    int a = blockIdx.x;

    // ---- segment of sorted idx_i equal to a ----
    int pstart, pend;
    if constexpr (FIRST) {
        if (f < 32) {
            int ps = warp_bound(idx_i, a, false);
            int pe = warp_bound(idx_i, a, true);
            if (f == 0) {
                s_seg[0] = ps; s_seg[1] = pe;
                g_seg[a] = make_int2(ps, pe);
            }
        }
        __syncthreads();
        pstart = s_seg[0]; pend = s_seg[1];
    } else {
        int2 se = __ldg(&g_seg[a]);
        pstart = se.x; pend = se.y;
    }

    // preload Wf column f (this t) + bias
    float wfr[NL][NRBF];
    {
        const float* wf = Wf + T * (NRBF * NL * FDIM) + f;
        #pragma unroll
        for (int k = 0; k < NRBF; k++)
            #pragma unroll
            for (int l = 0; l < NL; l++)
                wfr[l][k] = __ldg(wf + k * NL * FDIM + l * FDIM);
    }
    float bfl[NL];
    #pragma unroll
    for (int l = 0; l < NL; l++) bfl[l] = __ldg(bfv + T * NL * FDIM + l * FDIM + f);

    float dxr[9];
    #pragma unroll
    for (int o = 0; o < 9; o++) dxr[o] = 0.f;

    const float width = CUTOFF / (NRBF - 1);
    const float alpha = -0.5f / (width * width);

    for (int c = pstart; c < pend; c += CH) {
        int n = min(CH, pend - c);
        if (f < n) {
            int p = c + f;
            int jj = __ldg(idx_j + p);
            s_j[f] = FIRST ? __ldg(Z + jj) : jj;
            float rx = __ldg(r_ij + 3 * p), ry = __ldg(r_ij + 3 * p + 1),
                  rz = __ldg(r_ij + 3 * p + 2);
            float d = sqrtf(rx * rx + ry * ry + rz * rz);
            float cut = (d < CUTOFF)
                      ? 0.5f * (cosf(d * (3.14159265358979323846f / CUTOFF)) + 1.f) : 0.f;
            s_cut[f] = cut;
            #pragma unroll
            for (int k = 0; k < NRBF; k++) {
                float dd = d - width * (float)k;
                s_rad[f][k] = __expf(alpha * dd * dd) * cut;
            }
            float inv = 1.f / d;
            float x = rx * inv, y = ry * inv, z = rz * inv;
            const float c0 = 0.28209479177387814f;
            const float c1 = 0.4886025119029199f;
            const float c2 = 1.0925484305920792f;
            const float c3 = 0.31539156525252005f;
            const float c4 = 0.5462742152960396f;
            s_Y[f][0] = c0;
            s_Y[f][1] = c1 * y;
            s_Y[f][2] = c1 * z;
            s_Y[f][3] = c1 * x;
            s_Y[f][4] = c2 * x * y;
            s_Y[f][5] = c2 * y * z;
            s_Y[f][6] = c3 * (3.f * z * z - 1.f);
            s_Y[f][7] = c2 * x * z;
            s_Y[f][8] = c4 * (x * x - y * y);
        }
        __syncthreads();

        for (int i = 0; i < n; i++) {
            float cut = s_cut[i];
            float w0 = bfl[0] * cut, w1v = bfl[1] * cut, w2v = bfl[2] * cut;
            #pragma unroll
            for (int k = 0; k < NRBF; k++) {
                float r = s_rad[i][k];
                w0  = fmaf(r, wfr[0][k], w0);
                w1v = fmaf(r, wfr[1][k], w1v);
                w2v = fmaf(r, wfr[2][k], w2v);
            }
            float tv[9];
            tv[0] = s_Y[i][0] * w0;
            tv[1] = s_Y[i][1] * w1v;
            tv[2] = s_Y[i][2] * w1v;
            tv[3] = s_Y[i][3] * w1v;
            tv[4] = s_Y[i][4] * w2v;
            tv[5] = s_Y[i][5] * w2v;
            tv[6] = s_Y[i][6] * w2v;
            tv[7] = s_Y[i][7] * w2v;
            tv[8] = s_Y[i][8] * w2v;

            if constexpr (FIRST) {
                float x0 = __ldg(emb + s_j[i] * FDIM + f);
                const float cc[9] = {C0(0), C0(1), C0(2), C0(3), C0(4),
                                     C0(5), C0(6), C0(7), C0(8)};
                #pragma unroll
                for (int o = 0; o < 9; o++)
                    dxr[o] = fmaf(cc[o] * x0, tv[o], dxr[o]);
            } else {
                const float* xj = xin + s_j[i] * (NSH * FDIM) + f;
                float xr[9];
                #pragma unroll
                for (int o = 0; o < 9; o++) xr[o] = __ldg(xj + o * 64);
                Seg<0, 729>::run(dxr, xr, tv);
            }
        }
        __syncthreads();
    }

    // ---- update stage ----
    const float* w1 = W1 + T * 4096 + f;
    const float* w2 = W2 + T * 4096 + f;
    const float* w3 = W3 + T * 4096 + f;
    const float* wg = Wg + T * 12288 + f;
    const float* bgp = bg + T * 192 + f;
    int base = a * (NSH * FDIM);

    #pragma unroll
    for (int o = 0; o < 9; o++) sb0[o * 64 + f] = dxr[o];

    float w[64];
    #pragma unroll
    for (int k = 0; k < 64; k++) w[k] = __ldg(w1 + k * 64);
    __syncthreads();

    float ddx[9];
    const float4* a0p = reinterpret_cast<const float4*>(sb0);
    #pragma unroll
    for (int o = 0; o < 9; o++) {
        float s = 0.f;
        #pragma unroll
        for (int k4 = 0; k4 < 16; k4++) {
            float4 v = a0p[o * 16 + k4];
            s = fmaf(v.x, w[k4 * 4 + 0], s);
            s = fmaf(v.y, w[k4 * 4 + 1], s);
            s = fmaf(v.z, w[k4 * 4 + 2], s);
            s = fmaf(v.w, w[k4 * 4 + 3], s);
        }
        ddx[o] = s;
    }

    float tp[9];
    #pragma unroll
    for (int o = 0; o < 9; o++) tp[o] = dxr[o];
    Seg<0, 729>::run(tp, dxr, ddx);

    #pragma unroll
    for (int o = 0; o < 9; o++) sb1[o * 64 + f] = tp[o];

    #pragma unroll
    for (int k = 0; k < 64; k++) w[k] = __ldg(w2 + k * 64);
    __syncthreads();

    float dx2[9];
    const float4* a1p = reinterpret_cast<const float4*>(sb1);
    #pragma unroll
    for (int o = 0; o < 9; o++) {
        float s = 0.f;
        #pragma unroll
        for (int k4 = 0; k4 < 16; k4++) {
            float4 v = a1p[o * 16 + k4];
            s = fmaf(v.x, w[k4 * 4 + 0], s);
            s = fmaf(v.y, w[k4 * 4 + 1], s);
            s = fmaf(v.z, w[k4 * 4 + 2], s);
            s = fmaf(v.w, w[k4 * 4 + 3], s);
        }
        dx2[o] = s;
    }
    sb0[f] = dx2[0];
    __syncthreads();

    float g0 = bgp[0], g1 = bgp[64], g2 = bgp[128];
    {
        const float4* r0 = reinterpret_cast<const float4*>(sb0);
        #pragma unroll
        for (int k4 = 0; k4 < 16; k4++) {
            float4 v = r0[k4];
            const float* wgk = wg + (k4 * 4) * 192;
            g0 = fmaf(v.x, __ldg(wgk), g0);
            g1 = fmaf(v.x, __ldg(wgk + 64), g1);
            g2 = fmaf(v.x, __ldg(wgk + 128), g2);
            g0 = fmaf(v.y, __ldg(wgk + 192), g0);
            g1 = fmaf(v.y, __ldg(wgk + 256), g1);
            g2 = fmaf(v.y, __ldg(wgk + 320), g2);
            g0 = fmaf(v.z, __ldg(wgk + 384), g0);
            g1 = fmaf(v.z, __ldg(wgk + 448), g1);
            g2 = fmaf(v.z, __ldg(wgk + 512), g2);
            g0 = fmaf(v.w, __ldg(wgk + 576), g0);
            g1 = fmaf(v.w, __ldg(wgk + 640), g1);
            g2 = fmaf(v.w, __ldg(wgk + 704), g2);
        }
    }
    float sg[3];
    sg[0] = 1.f / (1.f + __expf(-g0));
    sg[1] = 1.f / (1.f + __expf(-g1));
    sg[2] = 1.f / (1.f + __expf(-g2));

    #pragma unroll
    for (int o = 0; o < 9; o++) {
        int l = (o >= 4) ? 2 : ((o >= 1) ? 1 : 0);
        sb1[o * 64 + f] = dx2[o] * sg[l];
    }

    #pragma unroll
    for (int k = 0; k < 64; k++) w[k] = __ldg(w3 + k * 64);
    __syncthreads();

    #pragma unroll
    for (int o = 0; o < 9; o++) {
        float s = 0.f;
        #pragma unroll
        for (int k4 = 0; k4 < 16; k4++) {
            float4 v = a1p[o * 16 + k4];
            s = fmaf(v.x, w[k4 * 4 + 0], s);
            s = fmaf(v.y, w[k4 * 4 + 1], s);
            s = fmaf(v.z, w[k4 * 4 + 2], s);
            s = fmaf(v.w, w[k4 * 4 + 3], s);
        }
        float prev;
        if constexpr (FIRST) {
            prev = (o == 0) ? __ldg(emb + __ldg(Z + a) * FDIM + f) : 0.f;
        } else {
            prev = __ldg(xin + base + o * 64 + f);
        }
        xw[base + o * 64 + f] = prev + s;
    }
}

// ---------------- launch ---------------------------------------------------
extern "C" void kernel_launch(void* const* d_in, const int* in_sizes, int n_in,
                              void* d_out, int out_size) {
    const int*   Z    = (const int*)d_in[0];
    const float* r_ij = (const float*)d_in[1];
    const int*   idxi = (const int*)d_in[2];
    const int*   idxj = (const int*)d_in[3];
    const float* emb  = (const float*)d_in[4];
    const float* Wf   = (const float*)d_in[5];
    const float* bf   = (const float*)d_in[6];
    const float* W1   = (const float*)d_in[7];
    const float* W2   = (const float*)d_in[8];
    const float* W3   = (const float*)d_in[9];
    const float* Wg   = (const float*)d_in[10];
    const float* bg   = (const float*)d_in[11];
    float* xout = (float*)d_out;

    float* x1;
    cudaGetSymbolAddress((void**)&x1, g_x1);

    // iter 0: emb -> g_x1 (and g_seg) ; iter 1: g_x1 -> xout
    fused_kernel<true ><<<NATOMS, 64>>>(idxi, idxj, Z, emb, r_ij, Wf, bf,
                                        nullptr, x1, W1, W2, W3, Wg, bg);
    fused_kernel<false><<<NATOMS, 64>>>(idxi, idxj, Z, emb, r_ij, Wf, bf,
                                        x1, xout, W1, W2, W3, Wg, bg);
}

// round 14
// speedup vs baseline: 1.4884x; 1.0087x over previous
#include <cuda_runtime.h>
#include <math.h>

#define NATOMS 1000
#define NPAIRS 10000
#define FDIM   64
#define NSH    9
#define YPAD   12
#define NL     3
#define NRBF   20
#define CUTOFF 5.0f
#define NITER  2
#define PCHUNK 64
#define PB     5

#define HDC __host__ __device__

// ---------------- device scratch (no allocations) -------------------------
__device__ float g_Y[NPAIRS * YPAD];
__device__ float g_Wij[NITER * NPAIRS * NL * FDIM];
__device__ float g_x1[NATOMS * NSH * FDIM];
__device__ float g_dx[NATOMS * NSH * FDIM];

// =================== compile-time real Clebsch-Gordan table ===============
HDC constexpr double cfact(int n) { double r = 1; for (int i = 2; i <= n; i++) r *= i; return r; }
HDC constexpr double csqrt_(double x) {
    if (x <= 0.0) return 0.0;
    double g = (x > 1.0) ? x : 1.0;
    for (int i = 0; i < 64; i++) g = 0.5 * (g + x / g);
    return g;
}
HDC constexpr int lof(int r) { return r >= 4 ? 2 : (r >= 1 ? 1 : 0); }

HDC constexpr double cg_c(int l1, int m1, int l2, int m2, int l3, int m3) {
    if (m3 != m1 + m2) return 0.0;
    int lmin = (l1 > l2) ? l1 - l2 : l2 - l1;
    if (l3 < lmin || l3 > l1 + l2) return 0.0;
    double pre = csqrt_((2.0 * l3 + 1.0) * cfact(l3 + l1 - l2) * cfact(l3 - l1 + l2) *
                        cfact(l1 + l2 - l3) / cfact(l1 + l2 + l3 + 1));
    pre *= csqrt_(cfact(l3 + m3) * cfact(l3 - m3) * cfact(l1 - m1) * cfact(l1 + m1) *
                  cfact(l2 - m2) * cfact(l2 + m2));
    double s = 0.0;
    for (int k = 0; k <= l1 + l2 - l3; k++) {
        int d2 = l1 - m1 - k, d3 = l2 + m2 - k, d4 = l3 - l2 + m1 + k, d5 = l3 - l1 - m2 + k;
        if (d2 < 0 || d3 < 0 || d4 < 0 || d5 < 0) continue;
        double denom = cfact(k) * cfact(l1 + l2 - l3 - k) * cfact(d2) * cfact(d3) *
                       cfact(d4) * cfact(d5);
        s += ((k & 1) ? -1.0 : 1.0) / denom;
    }
    return pre * s;
}

struct CRow { int n; int col[2]; double re[2]; double im[2]; };

HDC constexpr CRow urow(int r) {
    CRow s{}; int l = lof(r); int base = l * l + l; int mr = r - base;
    const double inv2 = 0.70710678118654752440;
    if (mr == 0) { s.n = 1; s.col[0] = base; s.re[0] = 1.0; s.im[0] = 0.0; }
    else if (mr > 0) {
        int m = mr; double sg = (m & 1) ? -1.0 : 1.0;
        s.n = 2;
        s.col[0] = base - m; s.re[0] = inv2;      s.im[0] = 0.0;
        s.col[1] = base + m; s.re[1] = sg * inv2; s.im[1] = 0.0;
    } else {
        int m = -mr; double sg = (m & 1) ? -1.0 : 1.0;
        s.n = 2;
        s.col[0] = base - m; s.re[0] = 0.0; s.im[0] = inv2;
        s.col[1] = base + m; s.re[1] = 0.0; s.im[1] = -sg * inv2;
    }
    return s;
}

HDC constexpr double real_cg(int o, int i2, int i3) {
    if (((lof(o) + lof(i2) + lof(i3)) & 1) != 0) return 0.0;
    CRow Ua = urow(i2), Ub = urow(i3), Uc = urow(o);
    int la = lof(i2), lb = lof(i3), lc = lof(o);
    int ba = la * la + la, bb = lb * lb + lb, bc = lc * lc + lc;
    double vre = 0.0;
    for (int i = 0; i < Ua.n; i++)
        for (int j = 0; j < Ub.n; j++)
            for (int k = 0; k < Uc.n; k++) {
                double cg = cg_c(la, Ua.col[i] - ba, lb, Ub.col[j] - bb, lc, Uc.col[k] - bc);
                if (cg == 0.0) continue;
                double t1r = Ua.re[i] * Ub.re[j] - Ua.im[i] * Ub.im[j];
                double t1i = Ua.re[i] * Ub.im[j] + Ua.im[i] * Ub.re[j];
                double tre = t1r * Uc.re[k] + t1i * Uc.im[k];
                vre += cg * tre;
            }
    return vre;
}

template <int LO, int HI>
struct Seg {
    static __device__ __forceinline__ void run(float (&acc)[9], const float (&a)[9],
                                               const float (&b)[9]) {
        if constexpr (HI - LO == 1) {
            constexpr int O = LO / 81, I2 = (LO / 9) % 9, I3 = LO % 9;
            constexpr double v = real_cg(O, I2, I3);
            if constexpr (v > 1e-9 || v < -1e-9) {
                acc[O] = fmaf((float)v, a[I2] * b[I3], acc[O]);
            }
        } else {
            Seg<LO, (LO + HI) / 2>::run(acc, a, b);
            Seg<(LO + HI) / 2, HI>::run(acc, a, b);
        }
    }
};

#define C0(o) ((float)real_cg(o, 0, o))

// ---- warp-parallel bound search over sorted idx_i ------------------------
__device__ __forceinline__ int warp_bound(const int* __restrict__ idx, int a, bool upper) {
    int lane = threadIdx.x & 31;
    int lo = 0, hiB = NPAIRS;
    while (hiB > lo) {
        int step = (hiB - lo + 31) >> 5;
        int pos = lo + lane * step;
        bool lt = false;
        if (pos < hiB) {
            int v = __ldg(idx + pos);
            lt = upper ? (v <= a) : (v < a);
        }
        unsigned m = __ballot_sync(0xffffffffu, lt);
        int c = __popc(m);
        if (c == 0) hiB = lo;
        else {
            int nlo = lo + (c - 1) * step + 1;
            int nhi = (c < 32) ? min(lo + c * step, hiB) : hiB;
            lo = nlo; hiB = nhi;
        }
    }
    return lo;
}

// ---------------- per-pair setup: blocked GEMM, Wf in registers (R8) ------
__global__ __launch_bounds__(256)
void pair_setup_kernel(const float* __restrict__ r_ij,
                       const float* __restrict__ Wf,
                       const float* __restrict__ bf) {
    __shared__ float s_rad[PCHUNK][NRBF];
    __shared__ float s_cut[PCHUNK];
    __shared__ float s_d[PCHUNK];

    int t = blockIdx.y;
    int p0 = blockIdx.x * PCHUNK;
    int tid = threadIdx.x;
    int f = tid & 63;
    int slot = tid >> 6;

    float w[NL][NRBF];
    const float* wf = Wf + t * (NRBF * NL * FDIM) + f;
    #pragma unroll
    for (int k = 0; k < NRBF; k++)
        #pragma unroll
        for (int l = 0; l < NL; l++)
            w[l][k] = __ldg(wf + k * NL * FDIM + l * FDIM);
    float bfl[NL];
    #pragma unroll
    for (int l = 0; l < NL; l++) bfl[l] = __ldg(bf + t * NL * FDIM + l * FDIM + f);

    if (tid < PCHUNK) {
        int p = p0 + tid;
        if (p < NPAIRS) {
            float rx = __ldg(r_ij + 3 * p), ry = __ldg(r_ij + 3 * p + 1),
                  rz = __ldg(r_ij + 3 * p + 2);
            float d = sqrtf(rx * rx + ry * ry + rz * rz);
            s_d[tid] = d;
            s_cut[tid] = (d < CUTOFF)
                       ? 0.5f * (cosf(d * (3.14159265358979323846f / CUTOFF)) + 1.f) : 0.f;
            if (blockIdx.y == 0) {
                float inv = 1.f / d;
                float x = rx * inv, y = ry * inv, z = rz * inv;
                const float c0 = 0.28209479177387814f;
                const float c1 = 0.4886025119029199f;
                const float c2 = 1.0925484305920792f;
                const float c3 = 0.31539156525252005f;
                const float c4 = 0.5462742152960396f;
                float4* yp = reinterpret_cast<float4*>(g_Y + p * YPAD);
                yp[0] = make_float4(c0, c1 * y, c1 * z, c1 * x);
                yp[1] = make_float4(c2 * x * y, c2 * y * z,
                                    c3 * (3.f * z * z - 1.f), c2 * x * z);
                yp[2] = make_float4(c4 * (x * x - y * y), 0.f, 0.f, 0.f);
            }
        }
    }
    __syncthreads();

    const float width = CUTOFF / (NRBF - 1);
    const float alpha = -0.5f / (width * width);
    for (int idx = tid; idx < PCHUNK * NRBF; idx += 256) {
        int pl = idx / NRBF, k = idx % NRBF;
        if (p0 + pl < NPAIRS) {
            float dd = s_d[pl] - width * (float)k;
            s_rad[pl][k] = __expf(alpha * dd * dd) * s_cut[pl];
        }
    }
    __syncthreads();

    float* wout = g_Wij + ((size_t)t * NPAIRS) * (NL * FDIM) + f;
    for (int pl = slot; pl < PCHUNK; pl += 4) {
        int p = p0 + pl;
        if (p >= NPAIRS) break;
        float cut = s_cut[pl];
        float s0 = bfl[0] * cut, s1 = bfl[1] * cut, s2 = bfl[2] * cut;
        const float4* rp = reinterpret_cast<const float4*>(s_rad[pl]);
        #pragma unroll
        for (int k4 = 0; k4 < 5; k4++) {
            float4 r = rp[k4];
            s0 = fmaf(r.x, w[0][k4 * 4 + 0], s0);
            s1 = fmaf(r.x, w[1][k4 * 4 + 0], s1);
            s2 = fmaf(r.x, w[2][k4 * 4 + 0], s2);
            s0 = fmaf(r.y, w[0][k4 * 4 + 1], s0);
            s1 = fmaf(r.y, w[1][k4 * 4 + 1], s1);
            s2 = fmaf(r.y, w[2][k4 * 4 + 1], s2);
            s0 = fmaf(r.z, w[0][k4 * 4 + 2], s0);
            s1 = fmaf(r.z, w[1][k4 * 4 + 2], s1);
            s2 = fmaf(r.z, w[2][k4 * 4 + 2], s2);
            s0 = fmaf(r.w, w[0][k4 * 4 + 3], s0);
            s1 = fmaf(r.w, w[1][k4 * 4 + 3], s1);
            s2 = fmaf(r.w, w[2][k4 * 4 + 3], s2);
        }
        float* wp = wout + (size_t)p * (NL * FDIM);
        wp[0]   = s0;
        wp[64]  = s1;
        wp[128] = s2;
    }
}

// ---------------- shared update-stage code (macro to reuse proven block) ----
// Inputs: dxr[9] (registers), f, T (0/1), prev[9], writes xw[base + ...]
__device__ __forceinline__ void update_stage(
    int f, int base, const float* __restrict__ W1, const float* __restrict__ W2,
    const float* __restrict__ W3, const float* __restrict__ Wg,
    const float* __restrict__ bg, int T,
    float (&dxr)[9], const float (&prev)[9], float* __restrict__ xw,
    float* sb0, float* sb1) {

    const float* w1 = W1 + T * 4096 + f;
    const float* w2 = W2 + T * 4096 + f;
    const float* w3 = W3 + T * 4096 + f;
    const float* wg = Wg + T * 12288 + f;
    const float* bgp = bg + T * 192 + f;

    #pragma unroll
    for (int o = 0; o < 9; o++) sb0[o * 64 + f] = dxr[o];

    float w[64];
    #pragma unroll
    for (int k = 0; k < 64; k++) w[k] = __ldg(w1 + k * 64);
    __syncthreads();

    float ddx[9];
    const float4* a0p = reinterpret_cast<const float4*>(sb0);
    #pragma unroll
    for (int o = 0; o < 9; o++) {
        float s = 0.f;
        #pragma unroll
        for (int k4 = 0; k4 < 16; k4++) {
            float4 v = a0p[o * 16 + k4];
            s = fmaf(v.x, w[k4 * 4 + 0], s);
            s = fmaf(v.y, w[k4 * 4 + 1], s);
            s = fmaf(v.z, w[k4 * 4 + 2], s);
            s = fmaf(v.w, w[k4 * 4 + 3], s);
        }
        ddx[o] = s;
    }

    float tp[9];
    #pragma unroll
    for (int o = 0; o < 9; o++) tp[o] = dxr[o];
    Seg<0, 729>::run(tp, dxr, ddx);

    #pragma unroll
    for (int o = 0; o < 9; o++) sb1[o * 64 + f] = tp[o];

    #pragma unroll
    for (int k = 0; k < 64; k++) w[k] = __ldg(w2 + k * 64);
    __syncthreads();

    float dx2[9];
    const float4* a1p = reinterpret_cast<const float4*>(sb1);
    #pragma unroll
    for (int o = 0; o < 9; o++) {
        float s = 0.f;
        #pragma unroll
        for (int k4 = 0; k4 < 16; k4++) {
            float4 v = a1p[o * 16 + k4];
            s = fmaf(v.x, w[k4 * 4 + 0], s);
            s = fmaf(v.y, w[k4 * 4 + 1], s);
            s = fmaf(v.z, w[k4 * 4 + 2], s);
            s = fmaf(v.w, w[k4 * 4 + 3], s);
        }
        dx2[o] = s;
    }
    sb0[f] = dx2[0];
    __syncthreads();

    float g0 = bgp[0], g1 = bgp[64], g2 = bgp[128];
    {
        const float4* r0 = reinterpret_cast<const float4*>(sb0);
        #pragma unroll
        for (int k4 = 0; k4 < 16; k4++) {
            float4 v = r0[k4];
            const float* wgk = wg + (k4 * 4) * 192;
            g0 = fmaf(v.x, __ldg(wgk), g0);
            g1 = fmaf(v.x, __ldg(wgk + 64), g1);
            g2 = fmaf(v.x, __ldg(wgk + 128), g2);
            g0 = fmaf(v.y, __ldg(wgk + 192), g0);
            g1 = fmaf(v.y, __ldg(wgk + 256), g1);
            g2 = fmaf(v.y, __ldg(wgk + 320), g2);
            g0 = fmaf(v.z, __ldg(wgk + 384), g0);
            g1 = fmaf(v.z, __ldg(wgk + 448), g1);
            g2 = fmaf(v.z, __ldg(wgk + 512), g2);
            g0 = fmaf(v.w, __ldg(wgk + 576), g0);
            g1 = fmaf(v.w, __ldg(wgk + 640), g1);
            g2 = fmaf(v.w, __ldg(wgk + 704), g2);
        }
    }
    float sg[3];
    sg[0] = 1.f / (1.f + __expf(-g0));
    sg[1] = 1.f / (1.f + __expf(-g1));
    sg[2] = 1.f / (1.f + __expf(-g2));

    #pragma unroll
    for (int o = 0; o < 9; o++) {
        int l = (o >= 4) ? 2 : ((o >= 1) ? 1 : 0);
        sb1[o * 64 + f] = dx2[o] * sg[l];
    }

    #pragma unroll
    for (int k = 0; k < 64; k++) w[k] = __ldg(w3 + k * 64);
    __syncthreads();

    #pragma unroll
    for (int o = 0; o < 9; o++) {
        float s = 0.f;
        #pragma unroll
        for (int k4 = 0; k4 < 16; k4++) {
            float4 v = a1p[o * 16 + k4];
            s = fmaf(v.x, w[k4 * 4 + 0], s);
            s = fmaf(v.y, w[k4 * 4 + 1], s);
            s = fmaf(v.z, w[k4 * 4 + 2], s);
            s = fmaf(v.w, w[k4 * 4 + 3], s);
        }
        xw[base + o * 64 + f] = prev[o] + s;
    }
}

// ---------------- t0: message (trivial scalar x) + update; zero g_dx -------
__global__ __launch_bounds__(64)
void fused_t0(const int* __restrict__ idx_i, const int* __restrict__ idx_j,
              const int* __restrict__ Z, const float* __restrict__ emb,
              const float* __restrict__ W1, const float* __restrict__ W2,
              const float* __restrict__ W3, const float* __restrict__ Wg,
              const float* __restrict__ bg) {
    __shared__ float sb0[NSH * FDIM];
    __shared__ float sb1[NSH * FDIM];
    __shared__ int   s_seg[2];

    int f = threadIdx.x;
    int a = blockIdx.x;
    int base = a * (NSH * FDIM);

    // zero g_dx for this atom (msg1 accumulates next launch)
    #pragma unroll
    for (int o = 0; o < 9; o++) g_dx[base + o * 64 + f] = 0.f;

    if (f < 32) {
        int ps = warp_bound(idx_i, a, false);
        int pe = warp_bound(idx_i, a, true);
        if (f == 0) { s_seg[0] = ps; s_seg[1] = pe; }
    }
    __syncthreads();
    int pstart = s_seg[0], pend = s_seg[1];

    float dxr[9];
    #pragma unroll
    for (int o = 0; o < 9; o++) dxr[o] = 0.f;

    const float* wbase = g_Wij + f;   // t = 0
    for (int p = pstart; p < pend; p++) {
        int j = __ldg(idx_j + p);
        float x0 = __ldg(emb + __ldg(Z + j) * FDIM + f);
        const float4* yp4 = reinterpret_cast<const float4*>(g_Y + p * YPAD);
        float4 y0 = yp4[0], y1 = yp4[1], y2 = yp4[2];
        const float* wp = wbase + (size_t)p * (NL * FDIM);
        float w0 = wp[0], w1v = wp[64], w2v = wp[128];
        dxr[0] = fmaf(C0(0) * x0, y0.x * w0,  dxr[0]);
        dxr[1] = fmaf(C0(1) * x0, y0.y * w1v, dxr[1]);
        dxr[2] = fmaf(C0(2) * x0, y0.z * w1v, dxr[2]);
        dxr[3] = fmaf(C0(3) * x0, y0.w * w1v, dxr[3]);
        dxr[4] = fmaf(C0(4) * x0, y1.x * w2v, dxr[4]);
        dxr[5] = fmaf(C0(5) * x0, y1.y * w2v, dxr[5]);
        dxr[6] = fmaf(C0(6) * x0, y1.z * w2v, dxr[6]);
        dxr[7] = fmaf(C0(7) * x0, y1.w * w2v, dxr[7]);
        dxr[8] = fmaf(C0(8) * x0, y2.x * w2v, dxr[8]);
    }

    float prev[9];
    prev[0] = __ldg(emb + __ldg(Z + a) * FDIM + f);
    #pragma unroll
    for (int o = 1; o < 9; o++) prev[o] = 0.f;

    update_stage(f, base, W1, W2, W3, Wg, bg, 0, dxr, prev, g_x1, sb0, sb1);
}

// ---------------- msg1: pair-parallel CG message with run-length atomics ---
__global__ __launch_bounds__(64, 14)
void msg1_kernel(const int* __restrict__ idx_i, const int* __restrict__ idx_j) {
    int f = threadIdx.x;
    int p0 = blockIdx.x * PB;
    if (p0 >= NPAIRS) return;

    const float* wbase = g_Wij + (size_t)NPAIRS * (NL * FDIM) + f;   // t = 1

    float dxr[9];
    #pragma unroll
    for (int o = 0; o < 9; o++) dxr[o] = 0.f;
    int cur = __ldg(idx_i + p0);

    #pragma unroll
    for (int k = 0; k < PB; k++) {
        int p = p0 + k;
        if (p >= NPAIRS) break;
        int ai = __ldg(idx_i + p);
        if (ai != cur) {
            float* dp = g_dx + cur * (NSH * FDIM) + f;
            #pragma unroll
            for (int o = 0; o < 9; o++) {
                atomicAdd(dp + o * 64, dxr[o]);
                dxr[o] = 0.f;
            }
            cur = ai;
        }
        int j = __ldg(idx_j + p);
        const float4* yp4 = reinterpret_cast<const float4*>(g_Y + p * YPAD);
        float4 y0 = yp4[0], y1 = yp4[1], y2 = yp4[2];
        const float* wp = wbase + (size_t)p * (NL * FDIM);
        float w0 = wp[0], w1v = wp[64], w2v = wp[128];
        float tv[9];
        tv[0] = y0.x * w0;
        tv[1] = y0.y * w1v;
        tv[2] = y0.z * w1v;
        tv[3] = y0.w * w1v;
        tv[4] = y1.x * w2v;
        tv[5] = y1.y * w2v;
        tv[6] = y1.z * w2v;
        tv[7] = y1.w * w2v;
        tv[8] = y2.x * w2v;
        const float* xj = g_x1 + j * (NSH * FDIM) + f;
        float xr[9];
        #pragma unroll
        for (int o = 0; o < 9; o++) xr[o] = __ldg(xj + o * 64);
        Seg<0, 729>::run(dxr, xr, tv);
    }
    {
        float* dp = g_dx + cur * (NSH * FDIM) + f;
        #pragma unroll
        for (int o = 0; o < 9; o++) atomicAdd(dp + o * 64, dxr[o]);
    }
}

// ---------------- upd1: update-only from g_dx, write final x ---------------
__global__ __launch_bounds__(64)
void upd1_kernel(float* __restrict__ xout,
                 const float* __restrict__ W1, const float* __restrict__ W2,
                 const float* __restrict__ W3, const float* __restrict__ Wg,
                 const float* __restrict__ bg) {
    __shared__ float sb0[NSH * FDIM];
    __shared__ float sb1[NSH * FDIM];
    int f = threadIdx.x;
    int a = blockIdx.x;
    int base = a * (NSH * FDIM);

    float dxr[9], prev[9];
    #pragma unroll
    for (int o = 0; o < 9; o++) {
        dxr[o]  = g_dx[base + o * 64 + f];
        prev[o] = __ldg(g_x1 + base + o * 64 + f);
    }
    update_stage(f, base, W1, W2, W3, Wg, bg, 1, dxr, prev, xout, sb0, sb1);
}

// ---------------- launch ---------------------------------------------------
extern "C" void kernel_launch(void* const* d_in, const int* in_sizes, int n_in,
                              void* d_out, int out_size) {
    const int*   Z    = (const int*)d_in[0];
    const float* r_ij = (const float*)d_in[1];
    const int*   idxi = (const int*)d_in[2];
    const int*   idxj = (const int*)d_in[3];
    const float* emb  = (const float*)d_in[4];
    const float* Wf   = (const float*)d_in[5];
    const float* bf   = (const float*)d_in[6];
    const float* W1   = (const float*)d_in[7];
    const float* W2   = (const float*)d_in[8];
    const float* W3   = (const float*)d_in[9];
    const float* Wg   = (const float*)d_in[10];
    const float* bg   = (const float*)d_in[11];
    float* xout = (float*)d_out;

    dim3 psgrid((NPAIRS + PCHUNK - 1) / PCHUNK, NITER);
    pair_setup_kernel<<<psgrid, 256>>>(r_ij, Wf, bf);
    fused_t0<<<NATOMS, 64>>>(idxi, idxj, Z, emb, W1, W2, W3, Wg, bg);
    msg1_kernel<<<(NPAIRS + PB - 1) / PB, 64>>>(idxi, idxj);
    upd1_kernel<<<NATOMS, 64>>>(xout, W1, W2, W3, Wg, bg);
}

// round 15
// speedup vs baseline: 1.5364x; 1.0322x over previous
#include <cuda_runtime.h>
#include <math.h>

#define NATOMS 1000
#define NPAIRS 10000
#define FDIM   64
#define NSH    9
#define YPAD   12
#define NL     3
#define NRBF   20
#define CUTOFF 5.0f
#define NITER  2
#define PCHUNK 64
#define PB     5

#define HDC __host__ __device__

// ---------------- device scratch (no allocations) -------------------------
__device__ float g_Y[NPAIRS * YPAD];
__device__ float g_Wij[NITER * NPAIRS * NL * FDIM];
__device__ float g_x1[NATOMS * NSH * FDIM];
__device__ float g_dx[NATOMS * NSH * FDIM];

// =================== compile-time real Clebsch-Gordan table ===============
HDC constexpr double cfact(int n) { double r = 1; for (int i = 2; i <= n; i++) r *= i; return r; }
HDC constexpr double csqrt_(double x) {
    if (x <= 0.0) return 0.0;
    double g = (x > 1.0) ? x : 1.0;
    for (int i = 0; i < 64; i++) g = 0.5 * (g + x / g);
    return g;
}
HDC constexpr int lof(int r) { return r >= 4 ? 2 : (r >= 1 ? 1 : 0); }

HDC constexpr double cg_c(int l1, int m1, int l2, int m2, int l3, int m3) {
    if (m3 != m1 + m2) return 0.0;
    int lmin = (l1 > l2) ? l1 - l2 : l2 - l1;
    if (l3 < lmin || l3 > l1 + l2) return 0.0;
    double pre = csqrt_((2.0 * l3 + 1.0) * cfact(l3 + l1 - l2) * cfact(l3 - l1 + l2) *
                        cfact(l1 + l2 - l3) / cfact(l1 + l2 + l3 + 1));
    pre *= csqrt_(cfact(l3 + m3) * cfact(l3 - m3) * cfact(l1 - m1) * cfact(l1 + m1) *
                  cfact(l2 - m2) * cfact(l2 + m2));
    double s = 0.0;
    for (int k = 0; k <= l1 + l2 - l3; k++) {
        int d2 = l1 - m1 - k, d3 = l2 + m2 - k, d4 = l3 - l2 + m1 + k, d5 = l3 - l1 - m2 + k;
        if (d2 < 0 || d3 < 0 || d4 < 0 || d5 < 0) continue;
        double denom = cfact(k) * cfact(l1 + l2 - l3 - k) * cfact(d2) * cfact(d3) *
                       cfact(d4) * cfact(d5);
        s += ((k & 1) ? -1.0 : 1.0) / denom;
    }
    return pre * s;
}

struct CRow { int n; int col[2]; double re[2]; double im[2]; };

HDC constexpr CRow urow(int r) {
    CRow s{}; int l = lof(r); int base = l * l + l; int mr = r - base;
    const double inv2 = 0.70710678118654752440;
    if (mr == 0) { s.n = 1; s.col[0] = base; s.re[0] = 1.0; s.im[0] = 0.0; }
    else if (mr > 0) {
        int m = mr; double sg = (m & 1) ? -1.0 : 1.0;
        s.n = 2;
        s.col[0] = base - m; s.re[0] = inv2;      s.im[0] = 0.0;
        s.col[1] = base + m; s.re[1] = sg * inv2; s.im[1] = 0.0;
    } else {
        int m = -mr; double sg = (m & 1) ? -1.0 : 1.0;
        s.n = 2;
        s.col[0] = base - m; s.re[0] = 0.0; s.im[0] = inv2;
        s.col[1] = base + m; s.re[1] = 0.0; s.im[1] = -sg * inv2;
    }
    return s;
}

HDC constexpr double real_cg(int o, int i2, int i3) {
    if (((lof(o) + lof(i2) + lof(i3)) & 1) != 0) return 0.0;
    CRow Ua = urow(i2), Ub = urow(i3), Uc = urow(o);
    int la = lof(i2), lb = lof(i3), lc = lof(o);
    int ba = la * la + la, bb = lb * lb + lb, bc = lc * lc + lc;
    double vre = 0.0;
    for (int i = 0; i < Ua.n; i++)
        for (int j = 0; j < Ub.n; j++)
            for (int k = 0; k < Uc.n; k++) {
                double cg = cg_c(la, Ua.col[i] - ba, lb, Ub.col[j] - bb, lc, Uc.col[k] - bc);
                if (cg == 0.0) continue;
                double t1r = Ua.re[i] * Ub.re[j] - Ua.im[i] * Ub.im[j];
                double t1i = Ua.re[i] * Ub.im[j] + Ua.im[i] * Ub.re[j];
                double tre = t1r * Uc.re[k] + t1i * Uc.im[k];
                vre += cg * tre;
            }
    return vre;
}

template <int LO, int HI>
struct Seg {
    static __device__ __forceinline__ void run(float (&acc)[9], const float (&a)[9],
                                               const float (&b)[9]) {
        if constexpr (HI - LO == 1) {
            constexpr int O = LO / 81, I2 = (LO / 9) % 9, I3 = LO % 9;
            constexpr double v = real_cg(O, I2, I3);
            if constexpr (v > 1e-9 || v < -1e-9) {
                acc[O] = fmaf((float)v, a[I2] * b[I3], acc[O]);
            }
        } else {
            Seg<LO, (LO + HI) / 2>::run(acc, a, b);
            Seg<(LO + HI) / 2, HI>::run(acc, a, b);
        }
    }
};

#define C0(o) ((float)real_cg(o, 0, o))

// ---- warp-parallel bound search over sorted idx_i ------------------------
__device__ __forceinline__ int warp_bound(const int* __restrict__ idx, int a, bool upper) {
    int lane = threadIdx.x & 31;
    int lo = 0, hiB = NPAIRS;
    while (hiB > lo) {
        int step = (hiB - lo + 31) >> 5;
        int pos = lo + lane * step;
        bool lt = false;
        if (pos < hiB) {
            int v = __ldg(idx + pos);
            lt = upper ? (v <= a) : (v < a);
        }
        unsigned m = __ballot_sync(0xffffffffu, lt);
        int c = __popc(m);
        if (c == 0) hiB = lo;
        else {
            int nlo = lo + (c - 1) * step + 1;
            int nhi = (c < 32) ? min(lo + c * step, hiB) : hiB;
            lo = nlo; hiB = nhi;
        }
    }
    return lo;
}

// ---------------- per-pair setup: blocked GEMM, Wf in registers -----------
__global__ __launch_bounds__(256)
void pair_setup_kernel(const float* __restrict__ r_ij,
                       const float* __restrict__ Wf,
                       const float* __restrict__ bf) {
    __shared__ float s_rad[PCHUNK][NRBF];
    __shared__ float s_cut[PCHUNK];
    __shared__ float s_d[PCHUNK];

    int t = blockIdx.y;
    int p0 = blockIdx.x * PCHUNK;
    int tid = threadIdx.x;
    int f = tid & 63;
    int slot = tid >> 6;

    float w[NL][NRBF];
    const float* wf = Wf + t * (NRBF * NL * FDIM) + f;
    #pragma unroll
    for (int k = 0; k < NRBF; k++)
        #pragma unroll
        for (int l = 0; l < NL; l++)
            w[l][k] = __ldg(wf + k * NL * FDIM + l * FDIM);
    float bfl[NL];
    #pragma unroll
    for (int l = 0; l < NL; l++) bfl[l] = __ldg(bf + t * NL * FDIM + l * FDIM + f);

    if (tid < PCHUNK) {
        int p = p0 + tid;
        if (p < NPAIRS) {
            float rx = __ldg(r_ij + 3 * p), ry = __ldg(r_ij + 3 * p + 1),
                  rz = __ldg(r_ij + 3 * p + 2);
            float d = sqrtf(rx * rx + ry * ry + rz * rz);
            s_d[tid] = d;
            s_cut[tid] = (d < CUTOFF)
                       ? 0.5f * (cosf(d * (3.14159265358979323846f / CUTOFF)) + 1.f) : 0.f;
            if (blockIdx.y == 0) {
                float inv = 1.f / d;
                float x = rx * inv, y = ry * inv, z = rz * inv;
                const float c0 = 0.28209479177387814f;
                const float c1 = 0.4886025119029199f;
                const float c2 = 1.0925484305920792f;
                const float c3 = 0.31539156525252005f;
                const float c4 = 0.5462742152960396f;
                float4* yp = reinterpret_cast<float4*>(g_Y + p * YPAD);
                yp[0] = make_float4(c0, c1 * y, c1 * z, c1 * x);
                yp[1] = make_float4(c2 * x * y, c2 * y * z,
                                    c3 * (3.f * z * z - 1.f), c2 * x * z);
                yp[2] = make_float4(c4 * (x * x - y * y), 0.f, 0.f, 0.f);
            }
        }
    }
    __syncthreads();

    const float width = CUTOFF / (NRBF - 1);
    const float alpha = -0.5f / (width * width);
    for (int idx = tid; idx < PCHUNK * NRBF; idx += 256) {
        int pl = idx / NRBF, k = idx % NRBF;
        if (p0 + pl < NPAIRS) {
            float dd = s_d[pl] - width * (float)k;
            s_rad[pl][k] = __expf(alpha * dd * dd) * s_cut[pl];
        }
    }
    __syncthreads();

    float* wout = g_Wij + ((size_t)t * NPAIRS) * (NL * FDIM) + f;
    for (int pl = slot; pl < PCHUNK; pl += 4) {
        int p = p0 + pl;
        if (p >= NPAIRS) break;
        float cut = s_cut[pl];
        float s0 = bfl[0] * cut, s1 = bfl[1] * cut, s2 = bfl[2] * cut;
        const float4* rp = reinterpret_cast<const float4*>(s_rad[pl]);
        #pragma unroll
        for (int k4 = 0; k4 < 5; k4++) {
            float4 r = rp[k4];
            s0 = fmaf(r.x, w[0][k4 * 4 + 0], s0);
            s1 = fmaf(r.x, w[1][k4 * 4 + 0], s1);
            s2 = fmaf(r.x, w[2][k4 * 4 + 0], s2);
            s0 = fmaf(r.y, w[0][k4 * 4 + 1], s0);
            s1 = fmaf(r.y, w[1][k4 * 4 + 1], s1);
            s2 = fmaf(r.y, w[2][k4 * 4 + 1], s2);
            s0 = fmaf(r.z, w[0][k4 * 4 + 2], s0);
            s1 = fmaf(r.z, w[1][k4 * 4 + 2], s1);
            s2 = fmaf(r.z, w[2][k4 * 4 + 2], s2);
            s0 = fmaf(r.w, w[0][k4 * 4 + 3], s0);
            s1 = fmaf(r.w, w[1][k4 * 4 + 3], s1);
            s2 = fmaf(r.w, w[2][k4 * 4 + 3], s2);
        }
        float* wp = wout + (size_t)p * (NL * FDIM);
        wp[0]   = s0;
        wp[64]  = s1;
        wp[128] = s2;
    }
}

// ---------------- update stage, 128 threads/atom (k-split GEMVs) ----------
// thread = (f, h): h in {0,1} owns k-range [h*32, h*32+32)
__device__ __forceinline__ void update_stage_h(
    int f, int h, int base,
    const float* __restrict__ W1, const float* __restrict__ W2,
    const float* __restrict__ W3, const float* __restrict__ Wg,
    const float* __restrict__ bg, int T,
    const float (&dxr)[9], const float (&prev)[9], float* __restrict__ xw,
    float* sbA, float* sbB, float* sbP) {

    const float* w1 = W1 + T * 4096 + f;
    const float* w2 = W2 + T * 4096 + f;
    const float* w3 = W3 + T * 4096 + f;
    const float* wg = Wg + T * 12288 + f;
    const float* bgp = bg + T * 192 + f;

    float w[32];

    // ---- GEMV1: ddx = dx @ W1 ----
    if (h == 0) {
        #pragma unroll
        for (int o = 0; o < 9; o++) sbA[o * 64 + f] = dxr[o];
    }
    #pragma unroll
    for (int k = 0; k < 32; k++) w[k] = __ldg(w1 + (h * 32 + k) * 64);
    __syncthreads();
    {
        const float4* a4 = reinterpret_cast<const float4*>(sbA);
        #pragma unroll
        for (int o = 0; o < 9; o++) {
            float s = 0.f;
            #pragma unroll
            for (int k4 = 0; k4 < 8; k4++) {
                float4 v = a4[o * 16 + h * 8 + k4];
                s = fmaf(v.x, w[k4 * 4 + 0], s);
                s = fmaf(v.y, w[k4 * 4 + 1], s);
                s = fmaf(v.z, w[k4 * 4 + 2], s);
                s = fmaf(v.w, w[k4 * 4 + 3], s);
            }
            sbP[h * 576 + o * 64 + f] = s;
        }
    }
    __syncthreads();
    float ddx[9];
    #pragma unroll
    for (int o = 0; o < 9; o++) ddx[o] = sbP[o * 64 + f] + sbP[576 + o * 64 + f];

    // ---- tp = dx + CG(dx, ddx) (redundant in both halves) ----
    float tp[9];
    #pragma unroll
    for (int o = 0; o < 9; o++) tp[o] = dxr[o];
    Seg<0, 729>::run(tp, dxr, ddx);

    // ---- GEMV2: dx2 = tp @ W2 ----
    if (h == 0) {
        #pragma unroll
        for (int o = 0; o < 9; o++) sbB[o * 64 + f] = tp[o];
    }
    #pragma unroll
    for (int k = 0; k < 32; k++) w[k] = __ldg(w2 + (h * 32 + k) * 64);
    __syncthreads();
    {
        const float4* b4 = reinterpret_cast<const float4*>(sbB);
        #pragma unroll
        for (int o = 0; o < 9; o++) {
            float s = 0.f;
            #pragma unroll
            for (int k4 = 0; k4 < 8; k4++) {
                float4 v = b4[o * 16 + h * 8 + k4];
                s = fmaf(v.x, w[k4 * 4 + 0], s);
                s = fmaf(v.y, w[k4 * 4 + 1], s);
                s = fmaf(v.z, w[k4 * 4 + 2], s);
                s = fmaf(v.w, w[k4 * 4 + 3], s);
            }
            sbP[h * 576 + o * 64 + f] = s;
        }
    }
    __syncthreads();
    float dx2[9];
    #pragma unroll
    for (int o = 0; o < 9; o++) dx2[o] = sbP[o * 64 + f] + sbP[576 + o * 64 + f];

    // ---- gate = sigmoid(dx2[0,:] @ Wg + bg), k-split ----
    if (h == 0) sbA[f] = dx2[0];
    __syncthreads();
    float g0 = 0.f, g1 = 0.f, g2 = 0.f;
    {
        const float4* r0 = reinterpret_cast<const float4*>(sbA);
        #pragma unroll
        for (int k4 = 0; k4 < 8; k4++) {
            float4 v = r0[h * 8 + k4];
            const float* wgk = wg + (h * 32 + k4 * 4) * 192;
            g0 = fmaf(v.x, __ldg(wgk), g0);
            g1 = fmaf(v.x, __ldg(wgk + 64), g1);
            g2 = fmaf(v.x, __ldg(wgk + 128), g2);
            g0 = fmaf(v.y, __ldg(wgk + 192), g0);
            g1 = fmaf(v.y, __ldg(wgk + 256), g1);
            g2 = fmaf(v.y, __ldg(wgk + 320), g2);
            g0 = fmaf(v.z, __ldg(wgk + 384), g0);
            g1 = fmaf(v.z, __ldg(wgk + 448), g1);
            g2 = fmaf(v.z, __ldg(wgk + 512), g2);
            g0 = fmaf(v.w, __ldg(wgk + 576), g0);
            g1 = fmaf(v.w, __ldg(wgk + 640), g1);
            g2 = fmaf(v.w, __ldg(wgk + 704), g2);
        }
    }
    sbP[h * 576 + 0 * 64 + f] = g0;
    sbP[h * 576 + 1 * 64 + f] = g1;
    sbP[h * 576 + 2 * 64 + f] = g2;
    __syncthreads();
    float sg[3];
    sg[0] = 1.f / (1.f + __expf(-(sbP[0 * 64 + f] + sbP[576 + 0 * 64 + f] + bgp[0])));
    sg[1] = 1.f / (1.f + __expf(-(sbP[1 * 64 + f] + sbP[576 + 1 * 64 + f] + bgp[64])));
    sg[2] = 1.f / (1.f + __expf(-(sbP[2 * 64 + f] + sbP[576 + 2 * 64 + f] + bgp[128])));

    // ---- GEMV3: out = (dx2 * sg[l]) @ W3 ; xw = prev + out ----
    __syncthreads();   // sbB reads (GEMV2) done; safe to overwrite
    if (h == 0) {
        #pragma unroll
        for (int o = 0; o < 9; o++) {
            int l = (o >= 4) ? 2 : ((o >= 1) ? 1 : 0);
            sbB[o * 64 + f] = dx2[o] * sg[l];
        }
    }
    #pragma unroll
    for (int k = 0; k < 32; k++) w[k] = __ldg(w3 + (h * 32 + k) * 64);
    __syncthreads();
    {
        const float4* b4 = reinterpret_cast<const float4*>(sbB);
        #pragma unroll
        for (int o = 0; o < 9; o++) {
            float s = 0.f;
            #pragma unroll
            for (int k4 = 0; k4 < 8; k4++) {
                float4 v = b4[o * 16 + h * 8 + k4];
                s = fmaf(v.x, w[k4 * 4 + 0], s);
                s = fmaf(v.y, w[k4 * 4 + 1], s);
                s = fmaf(v.z, w[k4 * 4 + 2], s);
                s = fmaf(v.w, w[k4 * 4 + 3], s);
            }
            sbP[h * 576 + o * 64 + f] = s;
        }
    }
    __syncthreads();
    if (h == 0) {
        #pragma unroll
        for (int o = 0; o < 9; o++)
            xw[base + o * 64 + f] = prev[o] + sbP[o * 64 + f] + sbP[576 + o * 64 + f];
    }
}

// ---------------- t0: message (scalar x, split by half) + update ----------
__global__ __launch_bounds__(128)
void fused_t0(const int* __restrict__ idx_i, const int* __restrict__ idx_j,
              const int* __restrict__ Z, const float* __restrict__ emb,
              const float* __restrict__ W1, const float* __restrict__ W2,
              const float* __restrict__ W3, const float* __restrict__ Wg,
              const float* __restrict__ bg) {
    __shared__ float sbA[NSH * FDIM];
    __shared__ float sbB[NSH * FDIM];
    __shared__ float sbP[2 * NSH * FDIM];
    __shared__ int   s_seg[2];

    int tid = threadIdx.x;
    int f = tid & 63;
    int h = tid >> 6;
    int a = blockIdx.x;
    int base = a * (NSH * FDIM);

    // zero g_dx for this atom
    for (int i = tid; i < NSH * FDIM; i += 128) g_dx[base + i] = 0.f;

    if (tid < 32) {
        int ps = warp_bound(idx_i, a, false);
        int pe = warp_bound(idx_i, a, true);
        if (tid == 0) { s_seg[0] = ps; s_seg[1] = pe; }
    }
    __syncthreads();
    int pstart = s_seg[0], pend = s_seg[1];

    // message: halves take alternating pairs
    float dxr[9];
    #pragma unroll
    for (int o = 0; o < 9; o++) dxr[o] = 0.f;

    const float* wbase = g_Wij + f;   // t = 0
    for (int p = pstart + h; p < pend; p += 2) {
        int j = __ldg(idx_j + p);
        float x0 = __ldg(emb + __ldg(Z + j) * FDIM + f);
        const float4* yp4 = reinterpret_cast<const float4*>(g_Y + p * YPAD);
        float4 y0 = yp4[0], y1 = yp4[1], y2 = yp4[2];
        const float* wp = wbase + (size_t)p * (NL * FDIM);
        float w0 = wp[0], w1v = wp[64], w2v = wp[128];
        dxr[0] = fmaf(C0(0) * x0, y0.x * w0,  dxr[0]);
        dxr[1] = fmaf(C0(1) * x0, y0.y * w1v, dxr[1]);
        dxr[2] = fmaf(C0(2) * x0, y0.z * w1v, dxr[2]);
        dxr[3] = fmaf(C0(3) * x0, y0.w * w1v, dxr[3]);
        dxr[4] = fmaf(C0(4) * x0, y1.x * w2v, dxr[4]);
        dxr[5] = fmaf(C0(5) * x0, y1.y * w2v, dxr[5]);
        dxr[6] = fmaf(C0(6) * x0, y1.z * w2v, dxr[6]);
        dxr[7] = fmaf(C0(7) * x0, y1.w * w2v, dxr[7]);
        dxr[8] = fmaf(C0(8) * x0, y2.x * w2v, dxr[8]);
    }
    // reduce halves
    #pragma unroll
    for (int o = 0; o < 9; o++) sbP[h * 576 + o * 64 + f] = dxr[o];
    __syncthreads();
    #pragma unroll
    for (int o = 0; o < 9; o++) dxr[o] = sbP[o * 64 + f] + sbP[576 + o * 64 + f];
    __syncthreads();

    float prev[9];
    prev[0] = __ldg(emb + __ldg(Z + a) * FDIM + f);
    #pragma unroll
    for (int o = 1; o < 9; o++) prev[o] = 0.f;

    update_stage_h(f, h, base, W1, W2, W3, Wg, bg, 0, dxr, prev, g_x1,
                   sbA, sbB, sbP);
}

// ---------------- msg1: pair-parallel CG message with run-length atomics ---
__global__ __launch_bounds__(64, 14)
void msg1_kernel(const int* __restrict__ idx_i, const int* __restrict__ idx_j) {
    int f = threadIdx.x;
    int p0 = blockIdx.x * PB;
    if (p0 >= NPAIRS) return;

    const float* wbase = g_Wij + (size_t)NPAIRS * (NL * FDIM) + f;   // t = 1

    float dxr[9];
    #pragma unroll
    for (int o = 0; o < 9; o++) dxr[o] = 0.f;
    int cur = __ldg(idx_i + p0);

    #pragma unroll
    for (int k = 0; k < PB; k++) {
        int p = p0 + k;
        if (p >= NPAIRS) break;
        int ai = __ldg(idx_i + p);
        if (ai != cur) {
            float* dp = g_dx + cur * (NSH * FDIM) + f;
            #pragma unroll
            for (int o = 0; o < 9; o++) {
                atomicAdd(dp + o * 64, dxr[o]);
                dxr[o] = 0.f;
            }
            cur = ai;
        }
        int j = __ldg(idx_j + p);
        const float4* yp4 = reinterpret_cast<const float4*>(g_Y + p * YPAD);
        float4 y0 = yp4[0], y1 = yp4[1], y2 = yp4[2];
        const float* wp = wbase + (size_t)p * (NL * FDIM);
        float w0 = wp[0], w1v = wp[64], w2v = wp[128];
        float tv[9];
        tv[0] = y0.x * w0;
        tv[1] = y0.y * w1v;
        tv[2] = y0.z * w1v;
        tv[3] = y0.w * w1v;
        tv[4] = y1.x * w2v;
        tv[5] = y1.y * w2v;
        tv[6] = y1.z * w2v;
        tv[7] = y1.w * w2v;
        tv[8] = y2.x * w2v;
        const float* xj = g_x1 + j * (NSH * FDIM) + f;
        float xr[9];
        #pragma unroll
        for (int o = 0; o < 9; o++) xr[o] = __ldg(xj + o * 64);
        Seg<0, 729>::run(dxr, xr, tv);
    }
    {
        float* dp = g_dx + cur * (NSH * FDIM) + f;
        #pragma unroll
        for (int o = 0; o < 9; o++) atomicAdd(dp + o * 64, dxr[o]);
    }
}

// ---------------- upd1: update-only from g_dx (128 threads/atom) -----------
__global__ __launch_bounds__(128)
void upd1_kernel(float* __restrict__ xout,
                 const float* __restrict__ W1, const float* __restrict__ W2,
                 const float* __restrict__ W3, const float* __restrict__ Wg,
                 const float* __restrict__ bg) {
    __shared__ float sbA[NSH * FDIM];
    __shared__ float sbB[NSH * FDIM];
    __shared__ float sbP[2 * NSH * FDIM];
    int tid = threadIdx.x;
    int f = tid & 63;
    int h = tid >> 6;
    int a = blockIdx.x;
    int base = a * (NSH * FDIM);

    float dxr[9], prev[9];
    #pragma unroll
    for (int o = 0; o < 9; o++) {
        dxr[o]  = g_dx[base + o * 64 + f];
        prev[o] = __ldg(g_x1 + base + o * 64 + f);
    }
    update_stage_h(f, h, base, W1, W2, W3, Wg, bg, 1, dxr, prev, xout,
                   sbA, sbB, sbP);
}

// ---------------- launch ---------------------------------------------------
extern "C" void kernel_launch(void* const* d_in, const int* in_sizes, int n_in,
                              void* d_out, int out_size) {
    const int*   Z    = (const int*)d_in[0];
    const float* r_ij = (const float*)d_in[1];
    const int*   idxi = (const int*)d_in[2];
    const int*   idxj = (const int*)d_in[3];
    const float* emb  = (const float*)d_in[4];
    const float* Wf   = (const float*)d_in[5];
    const float* bf   = (const float*)d_in[6];
    const float* W1   = (const float*)d_in[7];
    const float* W2   = (const float*)d_in[8];
    const float* W3   = (const float*)d_in[9];
    const float* Wg   = (const float*)d_in[10];
    const float* bg   = (const float*)d_in[11];
    float* xout = (float*)d_out;

    dim3 psgrid((NPAIRS + PCHUNK - 1) / PCHUNK, NITER);
    pair_setup_kernel<<<psgrid, 256>>>(r_ij, Wf, bf);
    fused_t0<<<NATOMS, 128>>>(idxi, idxj, Z, emb, W1, W2, W3, Wg, bg);
    msg1_kernel<<<(NPAIRS + PB - 1) / PB, 64>>>(idxi, idxj);
    upd1_kernel<<<NATOMS, 128>>>(xout, W1, W2, W3, Wg, bg);
}